// round 2
// baseline (speedup 1.0000x reference)
#include <cuda_runtime.h>
#include <cstdint>
#include <cstddef>

// Problem constants
#define TLEN   512
#define BATCH  4
#define HEADS  16
#define HDIM   64
#define EDIM   1024
#define ROWS_ALL 6144          // (1+NGRAM)*T * B = 1536*4
#define BH     64              // BATCH*HEADS
#define TGT    1536            // (1+NGRAM)*T

// ---------------- scratch (static device globals; no allocation) -------------
__device__ float g_q[(size_t)BH * TGT * HDIM];      // [bh][t_glob][d], q pre-scaled
__device__ float g_k[(size_t)BH * TGT * HDIM];
__device__ float g_v[(size_t)BH * TGT * HDIM];
__device__ float g_relvals[(size_t)ROWS_ALL * 512]; // [t_glob*B+b][bucket*H+h]
__device__ float g_ctx[(size_t)ROWS_ALL * EDIM];    // attention context, row = t_glob*B+b

// ---------------- shared SGEMM: C[M,N] = A[M,K] @ B[N,K]^T + bias ------------
// qkv_mode==1: scatter into g_q/g_k/g_v head-major layout (scale q by 0.125)
__global__ __launch_bounds__(256)
void sgemm_kernel(const float* __restrict__ A, const float* __restrict__ B,
                  const float* __restrict__ bias, float* __restrict__ C,
                  int M, int N, int K, int qkv_mode,
                  float* __restrict__ qp, float* __restrict__ kp, float* __restrict__ vp)
{
    __shared__ float As[16][132];
    __shared__ float Bs[16][132];
    const int tid = threadIdx.x;
    const int tx = tid & 15, ty = tid >> 4;
    const int bm = blockIdx.y, bn = blockIdx.x;
    const float* Ab = A + (size_t)bm * 128 * K;
    const float* Bb = B + (size_t)bn * 128 * K;

    float acc[8][8];
#pragma unroll
    for (int i = 0; i < 8; i++)
#pragma unroll
        for (int j = 0; j < 8; j++) acc[i][j] = 0.f;

    for (int k0 = 0; k0 < K; k0 += 16) {
#pragma unroll
        for (int qd = 0; qd < 2; qd++) {
            int p = tid + 256 * qd;          // 0..511
            int r = p >> 2;                  // 0..127
            int c4 = (p & 3) << 2;           // 0,4,8,12
            float4 av = *(const float4*)(Ab + (size_t)r * K + k0 + c4);
            As[c4 + 0][r] = av.x; As[c4 + 1][r] = av.y;
            As[c4 + 2][r] = av.z; As[c4 + 3][r] = av.w;
            float4 bv = *(const float4*)(Bb + (size_t)r * K + k0 + c4);
            Bs[c4 + 0][r] = bv.x; Bs[c4 + 1][r] = bv.y;
            Bs[c4 + 2][r] = bv.z; Bs[c4 + 3][r] = bv.w;
        }
        __syncthreads();
#pragma unroll
        for (int kk = 0; kk < 16; kk++) {
            float4 a0 = *(float4*)&As[kk][ty * 8];
            float4 a1 = *(float4*)&As[kk][ty * 8 + 4];
            float4 b0 = *(float4*)&Bs[kk][tx * 8];
            float4 b1 = *(float4*)&Bs[kk][tx * 8 + 4];
            float ar[8] = {a0.x, a0.y, a0.z, a0.w, a1.x, a1.y, a1.z, a1.w};
            float br[8] = {b0.x, b0.y, b0.z, b0.w, b1.x, b1.y, b1.z, b1.w};
#pragma unroll
            for (int i = 0; i < 8; i++)
#pragma unroll
                for (int j = 0; j < 8; j++) acc[i][j] += ar[i] * br[j];
        }
        __syncthreads();
    }

    const int row0 = bm * 128 + ty * 8;
    const int col0 = bn * 128 + tx * 8;
    if (!qkv_mode) {
#pragma unroll
        for (int i = 0; i < 8; i++) {
            float4 o0 = make_float4(acc[i][0] + bias[col0 + 0], acc[i][1] + bias[col0 + 1],
                                    acc[i][2] + bias[col0 + 2], acc[i][3] + bias[col0 + 3]);
            float4 o1 = make_float4(acc[i][4] + bias[col0 + 4], acc[i][5] + bias[col0 + 5],
                                    acc[i][6] + bias[col0 + 6], acc[i][7] + bias[col0 + 7]);
            *(float4*)&C[(size_t)(row0 + i) * N + col0]     = o0;
            *(float4*)&C[(size_t)(row0 + i) * N + col0 + 4] = o1;
        }
    } else {
        // col = which*1024 + h*64 + dd ; row = t_glob*4 + b
        const int which = col0 >> 10;
        const int e0 = col0 & 1023;
        const int hh = e0 >> 6;
        const int dd0 = e0 & 63;                 // multiple of 8, stays within head
        float* dst = (which == 0) ? qp : (which == 1) ? kp : vp;
        const float scale = (which == 0) ? 0.125f : 1.0f;   // d^-0.5, d=64
#pragma unroll
        for (int i = 0; i < 8; i++) {
            int row = row0 + i;
            int t = row >> 2, b = row & 3;
            float* base = dst + ((size_t)((b << 4) + hh) * TGT + t) * HDIM + dd0;
            float4 o0 = make_float4((acc[i][0] + bias[col0 + 0]) * scale,
                                    (acc[i][1] + bias[col0 + 1]) * scale,
                                    (acc[i][2] + bias[col0 + 2]) * scale,
                                    (acc[i][3] + bias[col0 + 3]) * scale);
            float4 o1 = make_float4((acc[i][4] + bias[col0 + 4]) * scale,
                                    (acc[i][5] + bias[col0 + 5]) * scale,
                                    (acc[i][6] + bias[col0 + 6]) * scale,
                                    (acc[i][7] + bias[col0 + 7]) * scale);
            *(float4*)&base[0] = o0;
            *(float4*)&base[4] = o1;
        }
    }
}

// ---------------- fused flash-style attention --------------------------------
// grid: (qt 0..7, bh 0..63, mode 0..2)  mode 0 = main, 1/2 = ngram 0/1
struct AttnSmem {
    float qT[64][68];      // [d][i]  transposed Q tile
    float kT[64][68];      // [d][j]  transposed K chunk
    float vS[64][68];      // [j][d]  V chunk
    float sS[64][68];      // [i][j]  logits
    float pT[64][68];      // [j][i]  probabilities (transposed)
    float relrow[64][32];  // rel values per (query row, bucket)
    float alpha[64];
    float lrow[64];
};

__global__ __launch_bounds__(256)
void attn_kernel(const float* __restrict__ q, const float* __restrict__ k,
                 const float* __restrict__ v, const float* __restrict__ relvals,
                 const int* __restrict__ bkm,   // i_buckets_main, plane b=0 (all planes equal)
                 const int* __restrict__ bkn,   // i_buckets_ngram, plane b=0
                 float* __restrict__ ctx)
{
    extern __shared__ char smraw[];
    AttnSmem& sm = *reinterpret_cast<AttnSmem*>(smraw);
    const int qt = blockIdx.x;
    const int bh = blockIdx.y;
    const int mode = blockIdx.z;
    const int b = bh >> 4, h = bh & 15;
    const int tid = threadIdx.x;
    const int tx = tid & 15, ty = tid >> 4;
    const int t0 = qt * 64;
    const int n = mode - 1;
    const int grow0 = mode * 512 + t0;   // global row base (q rows, hidden rows, ctx rows)

    // load Q tile (transposed) — already scaled
    {
        const float* qb = q + ((size_t)bh * TGT + grow0) * HDIM;
#pragma unroll
        for (int qd = 0; qd < 4; qd++) {
            int p = tid + 256 * qd;
            int r = p >> 4;
            int dd = (p & 15) << 2;
            float4 qv = *(const float4*)(qb + r * HDIM + dd);
            sm.qT[dd + 0][r] = qv.x; sm.qT[dd + 1][r] = qv.y;
            sm.qT[dd + 2][r] = qv.z; sm.qT[dd + 3][r] = qv.w;
        }
    }
    // preload rel values for all 32 buckets per query row (smem gather later)
    for (int idx = tid; idx < 64 * 32; idx += 256) {
        int i = idx >> 5, nb = idx & 31;
        sm.relrow[i][nb] = relvals[((size_t)(grow0 + i) * 4 + b) * 512 + nb * 16 + h];
    }

    float m_i = -1e30f, l_i = 0.f;       // online-softmax state (threads 0..63)
    float o[4][4];
#pragma unroll
    for (int i = 0; i < 4; i++)
#pragma unroll
        for (int j = 0; j < 4; j++) o[i][j] = 0.f;

    // mask structure: main needs chunks 0..qt; ngram needs 0..qt plus chunk 8+qt
    const int nloop = (mode == 0) ? (qt + 1) : (qt + 2);
    for (int ci = 0; ci < nloop; ci++) {
        const int sc = (mode != 0 && ci == qt + 1) ? (8 + qt) : ci;
        const int s0 = sc * 64;
        const int krow0 = (sc < 8) ? s0 : (n * 512 + s0);   // k_cat row mapping
        __syncthreads();
        {
            const float* kb = k + ((size_t)bh * TGT + krow0) * HDIM;
            const float* vb = v + ((size_t)bh * TGT + krow0) * HDIM;
#pragma unroll
            for (int qd = 0; qd < 4; qd++) {
                int p = tid + 256 * qd;
                int r = p >> 4;
                int dd = (p & 15) << 2;
                float4 kv = *(const float4*)(kb + r * HDIM + dd);
                sm.kT[dd + 0][r] = kv.x; sm.kT[dd + 1][r] = kv.y;
                sm.kT[dd + 2][r] = kv.z; sm.kT[dd + 3][r] = kv.w;
                float4 vv = *(const float4*)(vb + r * HDIM + dd);
                *(float4*)&sm.vS[r][dd] = vv;
            }
        }
        __syncthreads();

        // S = Q K^T  (4x4 microtile per thread)
        float sacc[4][4];
#pragma unroll
        for (int i = 0; i < 4; i++)
#pragma unroll
            for (int j = 0; j < 4; j++) sacc[i][j] = 0.f;
#pragma unroll 8
        for (int kk = 0; kk < 64; kk++) {
            float4 a  = *(float4*)&sm.qT[kk][ty * 4];
            float4 bb = *(float4*)&sm.kT[kk][tx * 4];
            float ar[4] = {a.x, a.y, a.z, a.w};
            float br[4] = {bb.x, bb.y, bb.z, bb.w};
#pragma unroll
            for (int i = 0; i < 4; i++)
#pragma unroll
                for (int j = 0; j < 4; j++) sacc[i][j] += ar[i] * br[j];
        }

        // add rel (smem lookup) + analytic mask, stage logits
#pragma unroll
        for (int ii = 0; ii < 4; ii++) {
            int i = ty * 4 + ii;
            int t_loc = t0 + i;
            int4 bk;
            if (mode == 0) bk = *(const int4*)(bkm + (size_t)t_loc * 512 + s0 + tx * 4);
            else           bk = *(const int4*)(bkn + (size_t)t_loc * 1024 + s0 + tx * 4);
            int bks[4] = {bk.x, bk.y, bk.z, bk.w};
#pragma unroll
            for (int jj = 0; jj < 4; jj++) {
                int s_g = s0 + tx * 4 + jj;
                float rel = sm.relrow[i][bks[jj]];
                bool allow;
                if (mode == 0) allow = (s_g <= t_loc);
                else allow = (s_g < 512) ? (s_g <= t_loc) : (s_g == 512 + t_loc);
                sm.sS[i][tx * 4 + jj] = sacc[ii][jj] + rel + (allow ? 0.f : -10000.f);
            }
        }
        __syncthreads();

        // online softmax row pass (one thread per row)
        if (tid < 64) {
            int i = tid;
            float mc = -1e30f;
#pragma unroll 8
            for (int j = 0; j < 64; j++) mc = fmaxf(mc, sm.sS[i][j]);
            float mnew = fmaxf(m_i, mc);
            float al = __expf(m_i - mnew);
            float ls = 0.f;
#pragma unroll 8
            for (int j = 0; j < 64; j++) {
                float e = __expf(sm.sS[i][j] - mnew);
                ls += e;
                sm.pT[j][i] = e;
            }
            l_i = l_i * al + ls;
            m_i = mnew;
            sm.alpha[i] = al;
        }
        __syncthreads();

        // O = O*alpha + P @ V
        float alr[4];
#pragma unroll
        for (int ii = 0; ii < 4; ii++) alr[ii] = sm.alpha[ty * 4 + ii];
#pragma unroll
        for (int ii = 0; ii < 4; ii++)
#pragma unroll
            for (int jj = 0; jj < 4; jj++) o[ii][jj] *= alr[ii];
#pragma unroll 8
        for (int j = 0; j < 64; j++) {
            float4 p4 = *(float4*)&sm.pT[j][ty * 4];
            float4 v4 = *(float4*)&sm.vS[j][tx * 4];
            float pr[4] = {p4.x, p4.y, p4.z, p4.w};
            float vr[4] = {v4.x, v4.y, v4.z, v4.w};
#pragma unroll
            for (int ii = 0; ii < 4; ii++)
#pragma unroll
                for (int jj = 0; jj < 4; jj++) o[ii][jj] += pr[ii] * vr[jj];
        }
    }
    __syncthreads();
    if (tid < 64) sm.lrow[tid] = l_i;
    __syncthreads();

    // write context: ctx[(grow*B + b)*E + h*64 + dd]
#pragma unroll
    for (int ii = 0; ii < 4; ii++) {
        int i = ty * 4 + ii;
        float inv = 1.0f / sm.lrow[i];
        float4 o4 = make_float4(o[ii][0] * inv, o[ii][1] * inv,
                                o[ii][2] * inv, o[ii][3] * inv);
        *(float4*)&ctx[((size_t)(grow0 + i) * 4 + b) * EDIM + h * 64 + tx * 4] = o4;
    }
}

// ---------------- launch -----------------------------------------------------
extern "C" void kernel_launch(void* const* d_in, const int* in_sizes, int n_in,
                              void* d_out, int out_size)
{
    const float* hidden = (const float*)d_in[0];
    const float* w_in   = (const float*)d_in[1];
    const float* b_in   = (const float*)d_in[2];
    const float* rel_w  = (const float*)d_in[3];
    const float* rel_b  = (const float*)d_in[4];
    const float* out_w  = (const float*)d_in[5];
    const float* out_b  = (const float*)d_in[6];
    // d_in[7] self_attn_mask, d_in[8] ngram_mask: computed analytically
    const int* bkm = (const int*)d_in[9];
    const int* bkn = (const int*)d_in[10];
    float* out = (float*)d_out;

    float *qp, *kp, *vp, *rv, *ctx;
    cudaGetSymbolAddress((void**)&qp,  g_q);
    cudaGetSymbolAddress((void**)&kp,  g_k);
    cudaGetSymbolAddress((void**)&vp,  g_v);
    cudaGetSymbolAddress((void**)&rv,  g_relvals);
    cudaGetSymbolAddress((void**)&ctx, g_ctx);

    // 1) QKV projection (scatter into head-major q/k/v, q scaled)
    sgemm_kernel<<<dim3(3072 / 128, 6144 / 128), 256>>>(
        hidden, w_in, b_in, nullptr, ROWS_ALL, 3 * EDIM, EDIM, 1, qp, kp, vp);

    // 2) rel values: hidden @ rel_w^T + rel_b
    sgemm_kernel<<<dim3(512 / 128, 6144 / 128), 256>>>(
        hidden, rel_w, rel_b, rv, ROWS_ALL, 512, EDIM, 0, nullptr, nullptr, nullptr);

    // 3) fused attention (main + 2 ngram streams)
    cudaFuncSetAttribute(attn_kernel, cudaFuncAttributeMaxDynamicSharedMemorySize,
                         (int)sizeof(AttnSmem));
    attn_kernel<<<dim3(8, 64, 3), 256, sizeof(AttnSmem)>>>(qp, kp, vp, rv, bkm, bkn, ctx);

    // 4) output projection: ctx @ out_w^T + out_b -> out
    sgemm_kernel<<<dim3(1024 / 128, 6144 / 128), 256>>>(
        ctx, out_w, out_b, out, ROWS_ALL, EDIM, EDIM, 0, nullptr, nullptr, nullptr);
}

// round 4
// speedup vs baseline: 1.7930x; 1.7930x over previous
#include <cuda_runtime.h>
#include <cuda_bf16.h>
#include <cstdint>
#include <cstddef>

// Problem constants
#define TLEN   512
#define BATCH  4
#define HEADS  16
#define HDIM   64
#define EDIM   1024
#define ROWS_ALL 6144          // (1+NGRAM)*T * B
#define BH     64
#define TGT    1536
#define KSPLIT 3072            // 3*EDIM (bf16 split-K)

// ---------------- scratch (static device globals; no allocation) -------------
__device__ float g_q[(size_t)BH * TGT * HDIM];
__device__ float g_k[(size_t)BH * TGT * HDIM];
__device__ float g_v[(size_t)BH * TGT * HDIM];
__device__ float g_relvals[(size_t)ROWS_ALL * 512];
__device__ float g_ctx[(size_t)ROWS_ALL * EDIM];
__device__ __nv_bfloat16 g_A2[(size_t)ROWS_ALL * KSPLIT];     // [hi|lo|hi] activations
__device__ __nv_bfloat16 g_Wqkv2[(size_t)3072 * KSPLIT];      // [hi|hi|lo] weights
__device__ __nv_bfloat16 g_Wrel2[(size_t)512 * KSPLIT];
__device__ __nv_bfloat16 g_Wout2[(size_t)1024 * KSPLIT];

__device__ __forceinline__ uint32_t smem_u32(const void* p) {
    uint32_t a;
    asm("{ .reg .u64 t; cvta.to.shared.u64 t, %1; cvt.u32.u64 %0, t; }" : "=r"(a) : "l"(p));
    return a;
}

// ---------------- bf16 split conversion --------------------------------------
// src: [rows][1024] f32 -> dst: [rows][3072] bf16.
// act=1: [hi|lo|hi]   act=0 (weights): [hi|hi|lo]
__global__ __launch_bounds__(256)
void convert_split(const float* __restrict__ src, __nv_bfloat16* __restrict__ dst, int act)
{
    int i4 = (blockIdx.x * blockDim.x + threadIdx.x) * 4;
    float4 a = *(const float4*)(src + i4);
    int r = i4 >> 10, k = i4 & 1023;
    size_t base = (size_t)r * KSPLIT + k;
    float av[4] = {a.x, a.y, a.z, a.w};
    __nv_bfloat16 h[4], l[4];
#pragma unroll
    for (int j = 0; j < 4; j++) {
        h[j] = __float2bfloat16(av[j]);
        l[j] = __float2bfloat16(av[j] - __bfloat162float(h[j]));
    }
    __nv_bfloat162 h01 = __halves2bfloat162(h[0], h[1]);
    __nv_bfloat162 h23 = __halves2bfloat162(h[2], h[3]);
    __nv_bfloat162 l01 = __halves2bfloat162(l[0], l[1]);
    __nv_bfloat162 l23 = __halves2bfloat162(l[2], l[3]);
    *(__nv_bfloat162*)(dst + base + 0) = h01;
    *(__nv_bfloat162*)(dst + base + 2) = h23;
    if (act) {
        *(__nv_bfloat162*)(dst + base + 1024) = l01;
        *(__nv_bfloat162*)(dst + base + 1026) = l23;
        *(__nv_bfloat162*)(dst + base + 2048) = h01;
        *(__nv_bfloat162*)(dst + base + 2050) = h23;
    } else {
        *(__nv_bfloat162*)(dst + base + 1024) = h01;
        *(__nv_bfloat162*)(dst + base + 1026) = h23;
        *(__nv_bfloat162*)(dst + base + 2048) = l01;
        *(__nv_bfloat162*)(dst + base + 2050) = l23;
    }
}

// ---------------- mma.sync bf16 GEMM (baseline-ISA tensor cores) --------------
// C[M,N] = A[M,K] @ B[N,K]^T + bias ; 128x128 CTA tile, BK=64, 4-stage cp.async
#define GSTAGES 4
#define STAGE_BYTES 16384
#define SMEM_A 0
#define SMEM_B (GSTAGES * STAGE_BYTES)
#define GEMM_SMEM (2 * GSTAGES * STAGE_BYTES)   // 128 KB

#define LOAD_STAGE(ld) do {                                                    \
        int _s = (ld) & 3;                                                     \
        uint32_t _ab = sb + SMEM_A + _s * STAGE_BYTES;                         \
        uint32_t _bb = sb + SMEM_B + _s * STAGE_BYTES;                         \
        const __nv_bfloat16* _ag = Ab + (ld) * 64;                             \
        const __nv_bfloat16* _bg = Bb + (ld) * 64;                             \
        _Pragma("unroll")                                                      \
        for (int _c = 0; _c < 4; _c++) {                                       \
            int _chunk = tid + _c * 256;                                       \
            int _row = _chunk >> 3, _c16 = _chunk & 7;                         \
            uint32_t _off = (uint32_t)(_row * 128 + _c16 * 16);                \
            _off ^= ((_off >> 3) & 0x70);                                      \
            asm volatile("cp.async.cg.shared.global [%0], [%1], 16;"           \
                :: "r"(_ab + _off), "l"(_ag + (size_t)_row * K + _c16 * 8));   \
            asm volatile("cp.async.cg.shared.global [%0], [%1], 16;"           \
                :: "r"(_bb + _off), "l"(_bg + (size_t)_row * K + _c16 * 8));   \
        }                                                                      \
        asm volatile("cp.async.commit_group;");                                \
    } while (0)

#define LDSM_X4(f, addr)                                                       \
    asm volatile("ldmatrix.sync.aligned.m8n8.x4.shared.b16 {%0,%1,%2,%3}, [%4];" \
        : "=r"((f)[0]), "=r"((f)[1]), "=r"((f)[2]), "=r"((f)[3]) : "r"(addr))

#define MMA16816(d, a, b0, b1)                                                 \
    asm volatile("mma.sync.aligned.m16n8k16.row.col.f32.bf16.bf16.f32 "        \
        "{%0,%1,%2,%3}, {%4,%5,%6,%7}, {%8,%9}, {%0,%1,%2,%3};"                \
        : "+f"((d)[0]), "+f"((d)[1]), "+f"((d)[2]), "+f"((d)[3])               \
        : "r"((a)[0]), "r"((a)[1]), "r"((a)[2]), "r"((a)[3]),                  \
          "r"(b0), "r"(b1))

__global__ __launch_bounds__(256, 1)
void gemm_mma(const __nv_bfloat16* __restrict__ A, const __nv_bfloat16* __restrict__ B,
              const float* __restrict__ bias, float* __restrict__ C,
              int N, int K, int qkv_mode,
              float* __restrict__ qp, float* __restrict__ kp, float* __restrict__ vp)
{
    extern __shared__ char smraw[];
    uint32_t sb = smem_u32(smraw);
    const int tid = threadIdx.x;
    const int wid = tid >> 5, lane = tid & 31;
    const int wm = wid & 3, wn = wid >> 2;       // warp tile: 32(m) x 64(n)
    const int bn = blockIdx.x, bm = blockIdx.y;
    const __nv_bfloat16* Ab = A + (size_t)bm * 128 * K;
    const __nv_bfloat16* Bb = B + (size_t)bn * 128 * K;
    const int NK = K >> 6;                       // 48

    float acc[2][8][4];
#pragma unroll
    for (int i = 0; i < 2; i++)
#pragma unroll
        for (int j = 0; j < 8; j++)
#pragma unroll
            for (int c = 0; c < 4; c++) acc[i][j][c] = 0.f;

    // ldmatrix per-lane addressing (TN layout, both operands K-contiguous)
    const int g = lane >> 3, r = lane & 7;
    // A: matrices [m0-7,k0][m8-15,k0][m0-7,k8][m8-15,k8]
    const int rowA = wm * 32 + (g & 1) * 8 + r;           // + mt*16
    const int achunk = (g >> 1);                           // + ks*2
    const uint32_t xa = (uint32_t)(rowA & 7);
    uint32_t aRowByte[2];
#pragma unroll
    for (int mt = 0; mt < 2; mt++) aRowByte[mt] = (uint32_t)((rowA + mt * 16) * 128);
    // B: matrices [n0-7,k0][n0-7,k8][n8-15,k0][n8-15,k8]
    const int rowB = wn * 64 + (g >> 1) * 8 + r;          // + nt2*16
    const int bchunk = (g & 1);                            // + ks*2
    const uint32_t xb = (uint32_t)(rowB & 7);
    uint32_t bRowByte[4];
#pragma unroll
    for (int nt2 = 0; nt2 < 4; nt2++) bRowByte[nt2] = (uint32_t)((rowB + nt2 * 16) * 128);

    LOAD_STAGE(0); LOAD_STAGE(1); LOAD_STAGE(2);

    for (int it = 0; it < NK; it++) {
        int pend = NK - 1 - it; if (pend > 2) pend = 2;
        switch (pend) {
            case 2: asm volatile("cp.async.wait_group 2;"); break;
            case 1: asm volatile("cp.async.wait_group 1;"); break;
            default: asm volatile("cp.async.wait_group 0;"); break;
        }
        __syncthreads();
        if (it + 3 < NK) LOAD_STAGE(it + 3);

        const uint32_t aB = sb + SMEM_A + (uint32_t)((it & 3) * STAGE_BYTES);
        const uint32_t bB = sb + SMEM_B + (uint32_t)((it & 3) * STAGE_BYTES);
#pragma unroll
        for (int ks = 0; ks < 4; ks++) {
            uint32_t af[2][4];
#pragma unroll
            for (int mt = 0; mt < 2; mt++)
                LDSM_X4(af[mt], aB + aRowByte[mt] +
                        ((uint32_t)((ks * 2 + achunk)) ^ xa) * 16u);
            uint32_t bf[4][4];
#pragma unroll
            for (int nt2 = 0; nt2 < 4; nt2++)
                LDSM_X4(bf[nt2], bB + bRowByte[nt2] +
                        ((uint32_t)((ks * 2 + bchunk)) ^ xb) * 16u);
#pragma unroll
            for (int mt = 0; mt < 2; mt++)
#pragma unroll
                for (int nt = 0; nt < 8; nt++) {
                    const uint32_t* bp = bf[nt >> 1];
                    int o = (nt & 1) * 2;
                    MMA16816(acc[mt][nt], af[mt], bp[o], bp[o + 1]);
                }
        }
    }

    // epilogue
    const int mrow0 = bm * 128 + wm * 32 + (lane >> 2);
    const int colb  = bn * 128 + wn * 64;
    if (!qkv_mode) {
#pragma unroll
        for (int mt = 0; mt < 2; mt++)
#pragma unroll
            for (int nt = 0; nt < 8; nt++) {
                int col = colb + nt * 8 + (lane & 3) * 2;
                float2 b2 = *(const float2*)&bias[col];
                int row = mrow0 + mt * 16;
                *(float2*)&C[(size_t)row * N + col] =
                    make_float2(acc[mt][nt][0] + b2.x, acc[mt][nt][1] + b2.y);
                *(float2*)&C[(size_t)(row + 8) * N + col] =
                    make_float2(acc[mt][nt][2] + b2.x, acc[mt][nt][3] + b2.y);
            }
    } else {
        const int which = colb >> 10;
        const int hh = (colb >> 6) & 15;
        float* dst = (which == 0) ? qp : (which == 1) ? kp : vp;
        const float scale = (which == 0) ? 0.125f : 1.0f;
#pragma unroll
        for (int mt = 0; mt < 2; mt++)
#pragma unroll
            for (int nt = 0; nt < 8; nt++) {
                int dd = nt * 8 + (lane & 3) * 2;
                float2 b2 = *(const float2*)&bias[colb + dd];
#pragma unroll
                for (int half = 0; half < 2; half++) {
                    int row = mrow0 + mt * 16 + half * 8;
                    int t = row >> 2, b3 = row & 3;
                    float* basep = dst + ((size_t)((b3 << 4) + hh) * TGT + t) * HDIM + dd;
                    *(float2*)basep = make_float2(
                        (acc[mt][nt][half * 2 + 0] + b2.x) * scale,
                        (acc[mt][nt][half * 2 + 1] + b2.y) * scale);
                }
            }
    }
}

// ---------------- fused flash-style attention (unchanged, passing) -----------
struct AttnSmem {
    float qT[64][68];
    float kT[64][68];
    float vS[64][68];
    float sS[64][68];
    float pT[64][68];
    float relrow[64][32];
    float alpha[64];
    float lrow[64];
};

__global__ __launch_bounds__(256)
void attn_kernel(const float* __restrict__ q, const float* __restrict__ k,
                 const float* __restrict__ v, const float* __restrict__ relvals,
                 const int* __restrict__ bkm, const int* __restrict__ bkn,
                 float* __restrict__ ctx)
{
    extern __shared__ char smraw[];
    AttnSmem& sm = *reinterpret_cast<AttnSmem*>(smraw);
    const int qt = blockIdx.x;
    const int bh = blockIdx.y;
    const int mode = blockIdx.z;
    const int b = bh >> 4, h = bh & 15;
    const int tid = threadIdx.x;
    const int tx = tid & 15, ty = tid >> 4;
    const int t0 = qt * 64;
    const int n = mode - 1;
    const int grow0 = mode * 512 + t0;

    {
        const float* qb = q + ((size_t)bh * TGT + grow0) * HDIM;
#pragma unroll
        for (int qd = 0; qd < 4; qd++) {
            int p = tid + 256 * qd;
            int r = p >> 4;
            int dd = (p & 15) << 2;
            float4 qv = *(const float4*)(qb + r * HDIM + dd);
            sm.qT[dd + 0][r] = qv.x; sm.qT[dd + 1][r] = qv.y;
            sm.qT[dd + 2][r] = qv.z; sm.qT[dd + 3][r] = qv.w;
        }
    }
    for (int idx = tid; idx < 64 * 32; idx += 256) {
        int i = idx >> 5, nb = idx & 31;
        sm.relrow[i][nb] = relvals[((size_t)(grow0 + i) * 4 + b) * 512 + nb * 16 + h];
    }

    float m_i = -1e30f, l_i = 0.f;
    float o[4][4];
#pragma unroll
    for (int i = 0; i < 4; i++)
#pragma unroll
        for (int j = 0; j < 4; j++) o[i][j] = 0.f;

    const int nloop = (mode == 0) ? (qt + 1) : (qt + 2);
    for (int ci = 0; ci < nloop; ci++) {
        const int sc = (mode != 0 && ci == qt + 1) ? (8 + qt) : ci;
        const int s0 = sc * 64;
        const int krow0 = (sc < 8) ? s0 : (n * 512 + s0);
        __syncthreads();
        {
            const float* kb = k + ((size_t)bh * TGT + krow0) * HDIM;
            const float* vb = v + ((size_t)bh * TGT + krow0) * HDIM;
#pragma unroll
            for (int qd = 0; qd < 4; qd++) {
                int p = tid + 256 * qd;
                int r = p >> 4;
                int dd = (p & 15) << 2;
                float4 kv = *(const float4*)(kb + r * HDIM + dd);
                sm.kT[dd + 0][r] = kv.x; sm.kT[dd + 1][r] = kv.y;
                sm.kT[dd + 2][r] = kv.z; sm.kT[dd + 3][r] = kv.w;
                float4 vv = *(const float4*)(vb + r * HDIM + dd);
                *(float4*)&sm.vS[r][dd] = vv;
            }
        }
        __syncthreads();

        float sacc[4][4];
#pragma unroll
        for (int i = 0; i < 4; i++)
#pragma unroll
            for (int j = 0; j < 4; j++) sacc[i][j] = 0.f;
#pragma unroll 8
        for (int kk = 0; kk < 64; kk++) {
            float4 a  = *(float4*)&sm.qT[kk][ty * 4];
            float4 bb = *(float4*)&sm.kT[kk][tx * 4];
            float ar[4] = {a.x, a.y, a.z, a.w};
            float br[4] = {bb.x, bb.y, bb.z, bb.w};
#pragma unroll
            for (int i = 0; i < 4; i++)
#pragma unroll
                for (int j = 0; j < 4; j++) sacc[i][j] += ar[i] * br[j];
        }

#pragma unroll
        for (int ii = 0; ii < 4; ii++) {
            int i = ty * 4 + ii;
            int t_loc = t0 + i;
            int4 bk;
            if (mode == 0) bk = *(const int4*)(bkm + (size_t)t_loc * 512 + s0 + tx * 4);
            else           bk = *(const int4*)(bkn + (size_t)t_loc * 1024 + s0 + tx * 4);
            int bks[4] = {bk.x, bk.y, bk.z, bk.w};
#pragma unroll
            for (int jj = 0; jj < 4; jj++) {
                int s_g = s0 + tx * 4 + jj;
                float rel = sm.relrow[i][bks[jj]];
                bool allow;
                if (mode == 0) allow = (s_g <= t_loc);
                else allow = (s_g < 512) ? (s_g <= t_loc) : (s_g == 512 + t_loc);
                sm.sS[i][tx * 4 + jj] = sacc[ii][jj] + rel + (allow ? 0.f : -10000.f);
            }
        }
        __syncthreads();

        if (tid < 64) {
            int i = tid;
            float mc = -1e30f;
#pragma unroll 8
            for (int j = 0; j < 64; j++) mc = fmaxf(mc, sm.sS[i][j]);
            float mnew = fmaxf(m_i, mc);
            float al = __expf(m_i - mnew);
            float ls = 0.f;
#pragma unroll 8
            for (int j = 0; j < 64; j++) {
                float e = __expf(sm.sS[i][j] - mnew);
                ls += e;
                sm.pT[j][i] = e;
            }
            l_i = l_i * al + ls;
            m_i = mnew;
            sm.alpha[i] = al;
        }
        __syncthreads();

        float alr[4];
#pragma unroll
        for (int ii = 0; ii < 4; ii++) alr[ii] = sm.alpha[ty * 4 + ii];
#pragma unroll
        for (int ii = 0; ii < 4; ii++)
#pragma unroll
            for (int jj = 0; jj < 4; jj++) o[ii][jj] *= alr[ii];
#pragma unroll 8
        for (int j = 0; j < 64; j++) {
            float4 p4 = *(float4*)&sm.pT[j][ty * 4];
            float4 v4 = *(float4*)&sm.vS[j][tx * 4];
            float pr[4] = {p4.x, p4.y, p4.z, p4.w};
            float vr[4] = {v4.x, v4.y, v4.z, v4.w};
#pragma unroll
            for (int ii = 0; ii < 4; ii++)
#pragma unroll
                for (int jj = 0; jj < 4; jj++) o[ii][jj] += pr[ii] * vr[jj];
        }
    }
    __syncthreads();
    if (tid < 64) sm.lrow[tid] = l_i;
    __syncthreads();

#pragma unroll
    for (int ii = 0; ii < 4; ii++) {
        int i = ty * 4 + ii;
        float inv = 1.0f / sm.lrow[i];
        float4 o4 = make_float4(o[ii][0] * inv, o[ii][1] * inv,
                                o[ii][2] * inv, o[ii][3] * inv);
        *(float4*)&ctx[((size_t)(grow0 + i) * 4 + b) * EDIM + h * 64 + tx * 4] = o4;
    }
}

// ---------------- launch -----------------------------------------------------
extern "C" void kernel_launch(void* const* d_in, const int* in_sizes, int n_in,
                              void* d_out, int out_size)
{
    const float* hidden = (const float*)d_in[0];
    const float* w_in   = (const float*)d_in[1];
    const float* b_in   = (const float*)d_in[2];
    const float* rel_w  = (const float*)d_in[3];
    const float* rel_b  = (const float*)d_in[4];
    const float* out_w  = (const float*)d_in[5];
    const float* out_b  = (const float*)d_in[6];
    const int* bkm = (const int*)d_in[9];
    const int* bkn = (const int*)d_in[10];
    float* out = (float*)d_out;

    float *qp, *kp, *vp, *rv, *ctx;
    __nv_bfloat16 *A2, *Wqkv2, *Wrel2, *Wout2;
    cudaGetSymbolAddress((void**)&qp,  g_q);
    cudaGetSymbolAddress((void**)&kp,  g_k);
    cudaGetSymbolAddress((void**)&vp,  g_v);
    cudaGetSymbolAddress((void**)&rv,  g_relvals);
    cudaGetSymbolAddress((void**)&ctx, g_ctx);
    cudaGetSymbolAddress((void**)&A2,    g_A2);
    cudaGetSymbolAddress((void**)&Wqkv2, g_Wqkv2);
    cudaGetSymbolAddress((void**)&Wrel2, g_Wrel2);
    cudaGetSymbolAddress((void**)&Wout2, g_Wout2);

    cudaFuncSetAttribute(gemm_mma, cudaFuncAttributeMaxDynamicSharedMemorySize, GEMM_SMEM);
    cudaFuncSetAttribute(attn_kernel, cudaFuncAttributeMaxDynamicSharedMemorySize,
                         (int)sizeof(AttnSmem));

    // 0) bf16 splits (activations [hi|lo|hi]; weights [hi|hi|lo])
    convert_split<<<ROWS_ALL, 256>>>(hidden, A2, 1);
    convert_split<<<3072, 256>>>(w_in,  Wqkv2, 0);
    convert_split<<<512,  256>>>(rel_w, Wrel2, 0);
    convert_split<<<1024, 256>>>(out_w, Wout2, 0);

    // 1) QKV projection (HMMA, scatter into head-major q/k/v, q scaled)
    gemm_mma<<<dim3(3072 / 128, ROWS_ALL / 128), 256, GEMM_SMEM>>>(
        A2, Wqkv2, b_in, nullptr, 3072, KSPLIT, 1, qp, kp, vp);

    // 2) rel values
    gemm_mma<<<dim3(512 / 128, ROWS_ALL / 128), 256, GEMM_SMEM>>>(
        A2, Wrel2, rel_b, rv, 512, KSPLIT, 0, nullptr, nullptr, nullptr);

    // 3) fused attention
    attn_kernel<<<dim3(8, 64, 3), 256, sizeof(AttnSmem)>>>(qp, kp, vp, rv, bkm, bkn, ctx);

    // 4) output projection
    convert_split<<<ROWS_ALL, 256>>>(ctx, A2, 1);
    gemm_mma<<<dim3(1024 / 128, ROWS_ALL / 128), 256, GEMM_SMEM>>>(
        A2, Wout2, out_b, out, 1024, KSPLIT, 0, nullptr, nullptr, nullptr);
}

// round 5
// speedup vs baseline: 1.9128x; 1.0668x over previous
#include <cuda_runtime.h>
#include <cuda_bf16.h>
#include <cstdint>
#include <cstddef>

// Problem constants
#define TLEN   512
#define BATCH  4
#define HEADS  16
#define HDIM   64
#define EDIM   1024
#define ROWS_ALL 6144          // (1+NGRAM)*T * B
#define BH     64
#define TGT    1536
#define KSPLIT 3072            // 3*EDIM (bf16 split-K)

// ---------------- scratch (static device globals; no allocation) -------------
__device__ float g_q[(size_t)BH * TGT * HDIM];
__device__ float g_k[(size_t)BH * TGT * HDIM];
__device__ float g_v[(size_t)BH * TGT * HDIM];
__device__ float g_relvals[(size_t)ROWS_ALL * 512];
__device__ float g_ctx[(size_t)ROWS_ALL * EDIM];
__device__ __nv_bfloat16 g_A2[(size_t)ROWS_ALL * KSPLIT];     // [hi|lo|hi] activations
__device__ __nv_bfloat16 g_Wqkv2[(size_t)3072 * KSPLIT];      // [hi|hi|lo] weights
__device__ __nv_bfloat16 g_Wrel2[(size_t)512 * KSPLIT];
__device__ __nv_bfloat16 g_Wout2[(size_t)1024 * KSPLIT];

__device__ __forceinline__ uint32_t smem_u32(const void* p) {
    uint32_t a;
    asm("{ .reg .u64 t; cvta.to.shared.u64 t, %1; cvt.u32.u64 %0, t; }" : "=r"(a) : "l"(p));
    return a;
}

// ---------------- bf16 split conversion --------------------------------------
__global__ __launch_bounds__(256)
void convert_split(const float* __restrict__ src, __nv_bfloat16* __restrict__ dst, int act)
{
    int i4 = (blockIdx.x * blockDim.x + threadIdx.x) * 4;
    float4 a = *(const float4*)(src + i4);
    int r = i4 >> 10, k = i4 & 1023;
    size_t base = (size_t)r * KSPLIT + k;
    float av[4] = {a.x, a.y, a.z, a.w};
    __nv_bfloat16 h[4], l[4];
#pragma unroll
    for (int j = 0; j < 4; j++) {
        h[j] = __float2bfloat16(av[j]);
        l[j] = __float2bfloat16(av[j] - __bfloat162float(h[j]));
    }
    __nv_bfloat162 h01 = __halves2bfloat162(h[0], h[1]);
    __nv_bfloat162 h23 = __halves2bfloat162(h[2], h[3]);
    __nv_bfloat162 l01 = __halves2bfloat162(l[0], l[1]);
    __nv_bfloat162 l23 = __halves2bfloat162(l[2], l[3]);
    *(__nv_bfloat162*)(dst + base + 0) = h01;
    *(__nv_bfloat162*)(dst + base + 2) = h23;
    if (act) {
        *(__nv_bfloat162*)(dst + base + 1024) = l01;
        *(__nv_bfloat162*)(dst + base + 1026) = l23;
        *(__nv_bfloat162*)(dst + base + 2048) = h01;
        *(__nv_bfloat162*)(dst + base + 2050) = h23;
    } else {
        *(__nv_bfloat162*)(dst + base + 1024) = h01;
        *(__nv_bfloat162*)(dst + base + 1026) = h23;
        *(__nv_bfloat162*)(dst + base + 2048) = l01;
        *(__nv_bfloat162*)(dst + base + 2050) = l23;
    }
}

// ---------------- mma.sync bf16 GEMM ------------------------------------------
#define GSTAGES 4
#define STAGE_BYTES 16384
#define SMEM_A 0
#define SMEM_B (GSTAGES * STAGE_BYTES)
#define GEMM_SMEM (2 * GSTAGES * STAGE_BYTES)   // 128 KB

#define LOAD_STAGE(ld) do {                                                    \
        int _s = (ld) & 3;                                                     \
        uint32_t _ab = sb + SMEM_A + _s * STAGE_BYTES;                         \
        uint32_t _bb = sb + SMEM_B + _s * STAGE_BYTES;                         \
        const __nv_bfloat16* _ag = Ab + (ld) * 64;                             \
        const __nv_bfloat16* _bg = Bb + (ld) * 64;                             \
        _Pragma("unroll")                                                      \
        for (int _c = 0; _c < 4; _c++) {                                       \
            int _chunk = tid + _c * 256;                                       \
            int _row = _chunk >> 3, _c16 = _chunk & 7;                         \
            uint32_t _off = (uint32_t)(_row * 128 + _c16 * 16);                \
            _off ^= ((_off >> 3) & 0x70);                                      \
            asm volatile("cp.async.cg.shared.global [%0], [%1], 16;"           \
                :: "r"(_ab + _off), "l"(_ag + (size_t)_row * K + _c16 * 8));   \
            asm volatile("cp.async.cg.shared.global [%0], [%1], 16;"           \
                :: "r"(_bb + _off), "l"(_bg + (size_t)_row * K + _c16 * 8));   \
        }                                                                      \
        asm volatile("cp.async.commit_group;");                                \
    } while (0)

#define LDSM_X4(f, addr)                                                       \
    asm volatile("ldmatrix.sync.aligned.m8n8.x4.shared.b16 {%0,%1,%2,%3}, [%4];" \
        : "=r"((f)[0]), "=r"((f)[1]), "=r"((f)[2]), "=r"((f)[3]) : "r"(addr))

#define MMA16816(d, a, b0, b1)                                                 \
    asm volatile("mma.sync.aligned.m16n8k16.row.col.f32.bf16.bf16.f32 "        \
        "{%0,%1,%2,%3}, {%4,%5,%6,%7}, {%8,%9}, {%0,%1,%2,%3};"                \
        : "+f"((d)[0]), "+f"((d)[1]), "+f"((d)[2]), "+f"((d)[3])               \
        : "r"((a)[0]), "r"((a)[1]), "r"((a)[2]), "r"((a)[3]),                  \
          "r"(b0), "r"(b1))

// fragment prefetch: overlap next-ks ldmatrix with current-ks MMAs
#define LOAD_FRAGS(buf, ks) do {                                               \
        _Pragma("unroll")                                                      \
        for (int _mt = 0; _mt < 2; _mt++)                                      \
            LDSM_X4(af[buf][_mt], aB + aRowByte[_mt] +                         \
                    ((uint32_t)(((ks) * 2 + achunk)) ^ xa) * 16u);             \
        _Pragma("unroll")                                                      \
        for (int _nt2 = 0; _nt2 < 4; _nt2++)                                   \
            LDSM_X4(bf[buf][_nt2], bB + bRowByte[_nt2] +                       \
                    ((uint32_t)(((ks) * 2 + bchunk)) ^ xb) * 16u);             \
    } while (0)

__global__ __launch_bounds__(256, 1)
void gemm_mma(const __nv_bfloat16* __restrict__ A, const __nv_bfloat16* __restrict__ B,
              const float* __restrict__ bias, float* __restrict__ C,
              int N, int K, int qkv_mode,
              float* __restrict__ qp, float* __restrict__ kp, float* __restrict__ vp)
{
    extern __shared__ char smraw[];
    uint32_t sb = smem_u32(smraw);
    const int tid = threadIdx.x;
    const int wid = tid >> 5, lane = tid & 31;
    const int wm = wid & 3, wn = wid >> 2;       // warp tile: 32(m) x 64(n)
    const int bn = blockIdx.x, bm = blockIdx.y;
    const __nv_bfloat16* Ab = A + (size_t)bm * 128 * K;
    const __nv_bfloat16* Bb = B + (size_t)bn * 128 * K;
    const int NK = K >> 6;                       // 48

    float acc[2][8][4];
#pragma unroll
    for (int i = 0; i < 2; i++)
#pragma unroll
        for (int j = 0; j < 8; j++)
#pragma unroll
            for (int c = 0; c < 4; c++) acc[i][j][c] = 0.f;

    const int g = lane >> 3, r = lane & 7;
    const int rowA = wm * 32 + (g & 1) * 8 + r;
    const int achunk = (g >> 1);
    const uint32_t xa = (uint32_t)(rowA & 7);
    uint32_t aRowByte[2];
#pragma unroll
    for (int mt = 0; mt < 2; mt++) aRowByte[mt] = (uint32_t)((rowA + mt * 16) * 128);
    const int rowB = wn * 64 + (g >> 1) * 8 + r;
    const int bchunk = (g & 1);
    const uint32_t xb = (uint32_t)(rowB & 7);
    uint32_t bRowByte[4];
#pragma unroll
    for (int nt2 = 0; nt2 < 4; nt2++) bRowByte[nt2] = (uint32_t)((rowB + nt2 * 16) * 128);

    LOAD_STAGE(0); LOAD_STAGE(1); LOAD_STAGE(2);

    uint32_t af[2][2][4];
    uint32_t bf[2][4][4];

    for (int it = 0; it < NK; it++) {
        int pend = NK - 1 - it; if (pend > 2) pend = 2;
        switch (pend) {
            case 2: asm volatile("cp.async.wait_group 2;"); break;
            case 1: asm volatile("cp.async.wait_group 1;"); break;
            default: asm volatile("cp.async.wait_group 0;"); break;
        }
        __syncthreads();
        if (it + 3 < NK) LOAD_STAGE(it + 3);

        const uint32_t aB = sb + SMEM_A + (uint32_t)((it & 3) * STAGE_BYTES);
        const uint32_t bB = sb + SMEM_B + (uint32_t)((it & 3) * STAGE_BYTES);

        LOAD_FRAGS(0, 0);
#pragma unroll
        for (int ks = 0; ks < 4; ks++) {
            const int cur = ks & 1;
            if (ks < 3) LOAD_FRAGS(cur ^ 1, ks + 1);
#pragma unroll
            for (int mt = 0; mt < 2; mt++)
#pragma unroll
                for (int nt = 0; nt < 8; nt++) {
                    const uint32_t* bp = bf[cur][nt >> 1];
                    int o = (nt & 1) * 2;
                    MMA16816(acc[mt][nt], af[cur][mt], bp[o], bp[o + 1]);
                }
        }
    }

    // epilogue
    const int mrow0 = bm * 128 + wm * 32 + (lane >> 2);
    const int colb  = bn * 128 + wn * 64;
    if (!qkv_mode) {
#pragma unroll
        for (int mt = 0; mt < 2; mt++)
#pragma unroll
            for (int nt = 0; nt < 8; nt++) {
                int col = colb + nt * 8 + (lane & 3) * 2;
                float2 b2 = *(const float2*)&bias[col];
                int row = mrow0 + mt * 16;
                *(float2*)&C[(size_t)row * N + col] =
                    make_float2(acc[mt][nt][0] + b2.x, acc[mt][nt][1] + b2.y);
                *(float2*)&C[(size_t)(row + 8) * N + col] =
                    make_float2(acc[mt][nt][2] + b2.x, acc[mt][nt][3] + b2.y);
            }
    } else {
        const int which = colb >> 10;
        const int hh = (colb >> 6) & 15;
        float* dst = (which == 0) ? qp : (which == 1) ? kp : vp;
        const float scale = (which == 0) ? 0.125f : 1.0f;
#pragma unroll
        for (int mt = 0; mt < 2; mt++)
#pragma unroll
            for (int nt = 0; nt < 8; nt++) {
                int dd = nt * 8 + (lane & 3) * 2;
                float2 b2 = *(const float2*)&bias[colb + dd];
#pragma unroll
                for (int half = 0; half < 2; half++) {
                    int row = mrow0 + mt * 16 + half * 8;
                    int t = row >> 2, b3 = row & 3;
                    float* basep = dst + ((size_t)((b3 << 4) + hh) * TGT + t) * HDIM + dd;
                    *(float2*)basep = make_float2(
                        (acc[mt][nt][half * 2 + 0] + b2.x) * scale,
                        (acc[mt][nt][half * 2 + 1] + b2.y) * scale);
                }
            }
    }
}

// ---------------- fused flash-style attention --------------------------------
struct AttnSmem {
    float qT[64][68];
    float kT[64][68];
    float vS[64][68];
    float sS[64][68];
    float pT[64][68];
    float relrow[64][32];
    float alpha[64];
    float lrow[64];
};

__global__ __launch_bounds__(256)
void attn_kernel(const float* __restrict__ q, const float* __restrict__ k,
                 const float* __restrict__ v, const float* __restrict__ relvals,
                 const int* __restrict__ bkm, const int* __restrict__ bkn,
                 float* __restrict__ ctx)
{
    extern __shared__ char smraw[];
    AttnSmem& sm = *reinterpret_cast<AttnSmem*>(smraw);
    const int qt = blockIdx.x;
    const int bh = blockIdx.y;
    const int mode = blockIdx.z;
    const int b = bh >> 4, h = bh & 15;
    const int tid = threadIdx.x;
    const int tx = tid & 15, ty = tid >> 4;
    const int t0 = qt * 64;
    const int n = mode - 1;
    const int grow0 = mode * 512 + t0;
    // softmax role: 4 threads per row
    const int srow = tid >> 2, spart = tid & 3;

    {
        const float* qb = q + ((size_t)bh * TGT + grow0) * HDIM;
#pragma unroll
        for (int qd = 0; qd < 4; qd++) {
            int p = tid + 256 * qd;
            int r = p >> 4;
            int dd = (p & 15) << 2;
            float4 qv = *(const float4*)(qb + r * HDIM + dd);
            sm.qT[dd + 0][r] = qv.x; sm.qT[dd + 1][r] = qv.y;
            sm.qT[dd + 2][r] = qv.z; sm.qT[dd + 3][r] = qv.w;
        }
    }
    for (int idx = tid; idx < 64 * 32; idx += 256) {
        int i = idx >> 5, nb = idx & 31;
        sm.relrow[i][nb] = relvals[((size_t)(grow0 + i) * 4 + b) * 512 + nb * 16 + h];
    }

    float m_i = -1e30f, l_i = 0.f;       // replicated across each 4-thread quad
    float o[4][4];
#pragma unroll
    for (int i = 0; i < 4; i++)
#pragma unroll
        for (int j = 0; j < 4; j++) o[i][j] = 0.f;

    const int nloop = (mode == 0) ? (qt + 1) : (qt + 2);
    for (int ci = 0; ci < nloop; ci++) {
        const int sc = (mode != 0 && ci == qt + 1) ? (8 + qt) : ci;
        const int s0 = sc * 64;
        const int krow0 = (sc < 8) ? s0 : (n * 512 + s0);
        __syncthreads();
        {
            const float* kb = k + ((size_t)bh * TGT + krow0) * HDIM;
            const float* vb = v + ((size_t)bh * TGT + krow0) * HDIM;
#pragma unroll
            for (int qd = 0; qd < 4; qd++) {
                int p = tid + 256 * qd;
                int r = p >> 4;
                int dd = (p & 15) << 2;
                float4 kv = *(const float4*)(kb + r * HDIM + dd);
                sm.kT[dd + 0][r] = kv.x; sm.kT[dd + 1][r] = kv.y;
                sm.kT[dd + 2][r] = kv.z; sm.kT[dd + 3][r] = kv.w;
                float4 vv = *(const float4*)(vb + r * HDIM + dd);
                *(float4*)&sm.vS[r][dd] = vv;
            }
        }
        __syncthreads();

        float sacc[4][4];
#pragma unroll
        for (int i = 0; i < 4; i++)
#pragma unroll
            for (int j = 0; j < 4; j++) sacc[i][j] = 0.f;
#pragma unroll 8
        for (int kk = 0; kk < 64; kk++) {
            float4 a  = *(float4*)&sm.qT[kk][ty * 4];
            float4 bb = *(float4*)&sm.kT[kk][tx * 4];
            float ar[4] = {a.x, a.y, a.z, a.w};
            float br[4] = {bb.x, bb.y, bb.z, bb.w};
#pragma unroll
            for (int i = 0; i < 4; i++)
#pragma unroll
                for (int j = 0; j < 4; j++) sacc[i][j] += ar[i] * br[j];
        }

#pragma unroll
        for (int ii = 0; ii < 4; ii++) {
            int i = ty * 4 + ii;
            int t_loc = t0 + i;
            int4 bk;
            if (mode == 0) bk = *(const int4*)(bkm + (size_t)t_loc * 512 + s0 + tx * 4);
            else           bk = *(const int4*)(bkn + (size_t)t_loc * 1024 + s0 + tx * 4);
            int bks[4] = {bk.x, bk.y, bk.z, bk.w};
#pragma unroll
            for (int jj = 0; jj < 4; jj++) {
                int s_g = s0 + tx * 4 + jj;
                float rel = sm.relrow[i][bks[jj]];
                bool allow;
                if (mode == 0) allow = (s_g <= t_loc);
                else allow = (s_g < 512) ? (s_g <= t_loc) : (s_g == 512 + t_loc);
                sm.sS[i][tx * 4 + jj] = sacc[ii][jj] + rel + (allow ? 0.f : -10000.f);
            }
        }
        __syncthreads();

        // online softmax: 4 threads per row (quad shuffle reduction)
        {
            const int i = srow;
            const int j0 = spart * 16;
            float mc = -1e30f;
#pragma unroll
            for (int j = 0; j < 16; j++) mc = fmaxf(mc, sm.sS[i][j0 + j]);
            mc = fmaxf(mc, __shfl_xor_sync(0xFFFFFFFFu, mc, 1));
            mc = fmaxf(mc, __shfl_xor_sync(0xFFFFFFFFu, mc, 2));
            float mnew = fmaxf(m_i, mc);
            float al = __expf(m_i - mnew);
            float ls = 0.f;
#pragma unroll
            for (int j = 0; j < 16; j++) {
                float e = __expf(sm.sS[i][j0 + j] - mnew);
                ls += e;
                sm.pT[j0 + j][i] = e;
            }
            ls += __shfl_xor_sync(0xFFFFFFFFu, ls, 1);
            ls += __shfl_xor_sync(0xFFFFFFFFu, ls, 2);
            l_i = l_i * al + ls;
            m_i = mnew;
            if (spart == 0) sm.alpha[i] = al;
        }
        __syncthreads();

        float alr[4];
#pragma unroll
        for (int ii = 0; ii < 4; ii++) alr[ii] = sm.alpha[ty * 4 + ii];
#pragma unroll
        for (int ii = 0; ii < 4; ii++)
#pragma unroll
            for (int jj = 0; jj < 4; jj++) o[ii][jj] *= alr[ii];
#pragma unroll 8
        for (int j = 0; j < 64; j++) {
            float4 p4 = *(float4*)&sm.pT[j][ty * 4];
            float4 v4 = *(float4*)&sm.vS[j][tx * 4];
            float pr[4] = {p4.x, p4.y, p4.z, p4.w};
            float vr[4] = {v4.x, v4.y, v4.z, v4.w};
#pragma unroll
            for (int ii = 0; ii < 4; ii++)
#pragma unroll
                for (int jj = 0; jj < 4; jj++) o[ii][jj] += pr[ii] * vr[jj];
        }
    }
    __syncthreads();
    if (spart == 0) sm.lrow[srow] = l_i;
    __syncthreads();

#pragma unroll
    for (int ii = 0; ii < 4; ii++) {
        int i = ty * 4 + ii;
        float inv = 1.0f / sm.lrow[i];
        float4 o4 = make_float4(o[ii][0] * inv, o[ii][1] * inv,
                                o[ii][2] * inv, o[ii][3] * inv);
        *(float4*)&ctx[((size_t)(grow0 + i) * 4 + b) * EDIM + h * 64 + tx * 4] = o4;
    }
}

// ---------------- launch -----------------------------------------------------
extern "C" void kernel_launch(void* const* d_in, const int* in_sizes, int n_in,
                              void* d_out, int out_size)
{
    const float* hidden = (const float*)d_in[0];
    const float* w_in   = (const float*)d_in[1];
    const float* b_in   = (const float*)d_in[2];
    const float* rel_w  = (const float*)d_in[3];
    const float* rel_b  = (const float*)d_in[4];
    const float* out_w  = (const float*)d_in[5];
    const float* out_b  = (const float*)d_in[6];
    const int* bkm = (const int*)d_in[9];
    const int* bkn = (const int*)d_in[10];
    float* out = (float*)d_out;

    float *qp, *kp, *vp, *rv, *ctx;
    __nv_bfloat16 *A2, *Wqkv2, *Wrel2, *Wout2;
    cudaGetSymbolAddress((void**)&qp,  g_q);
    cudaGetSymbolAddress((void**)&kp,  g_k);
    cudaGetSymbolAddress((void**)&vp,  g_v);
    cudaGetSymbolAddress((void**)&rv,  g_relvals);
    cudaGetSymbolAddress((void**)&ctx, g_ctx);
    cudaGetSymbolAddress((void**)&A2,    g_A2);
    cudaGetSymbolAddress((void**)&Wqkv2, g_Wqkv2);
    cudaGetSymbolAddress((void**)&Wrel2, g_Wrel2);
    cudaGetSymbolAddress((void**)&Wout2, g_Wout2);

    cudaFuncSetAttribute(gemm_mma, cudaFuncAttributeMaxDynamicSharedMemorySize, GEMM_SMEM);
    cudaFuncSetAttribute(attn_kernel, cudaFuncAttributeMaxDynamicSharedMemorySize,
                         (int)sizeof(AttnSmem));

    // 0) bf16 splits (activations [hi|lo|hi]; weights [hi|hi|lo])
    convert_split<<<ROWS_ALL, 256>>>(hidden, A2, 1);
    convert_split<<<3072, 256>>>(w_in,  Wqkv2, 0);
    convert_split<<<512,  256>>>(rel_w, Wrel2, 0);
    convert_split<<<1024, 256>>>(out_w, Wout2, 0);

    // 1) QKV projection (HMMA, scatter into head-major q/k/v, q scaled)
    gemm_mma<<<dim3(3072 / 128, ROWS_ALL / 128), 256, GEMM_SMEM>>>(
        A2, Wqkv2, b_in, nullptr, 3072, KSPLIT, 1, qp, kp, vp);

    // 2) rel values
    gemm_mma<<<dim3(512 / 128, ROWS_ALL / 128), 256, GEMM_SMEM>>>(
        A2, Wrel2, rel_b, rv, 512, KSPLIT, 0, nullptr, nullptr, nullptr);

    // 3) fused attention
    attn_kernel<<<dim3(8, 64, 3), 256, sizeof(AttnSmem)>>>(qp, kp, vp, rv, bkm, bkn, ctx);

    // 4) output projection
    convert_split<<<ROWS_ALL, 256>>>(ctx, A2, 1);
    gemm_mma<<<dim3(1024 / 128, ROWS_ALL / 128), 256, GEMM_SMEM>>>(
        A2, Wout2, out_b, out, 1024, KSPLIT, 0, nullptr, nullptr, nullptr);
}

// round 6
// speedup vs baseline: 2.3581x; 1.2328x over previous
#include <cuda_runtime.h>
#include <cuda_fp16.h>
#include <cstdint>
#include <cstddef>

// Problem constants
#define TLEN   512
#define BATCH  4
#define HEADS  16
#define HDIM   64
#define EDIM   1024
#define ROWS_ALL 6144          // (1+NGRAM)*T * B
#define BH     64
#define TGT    1536
#define KA     2048            // activation split-K (fp16 [hi|lo])
#define KB     1024            // weight K (fp16 hi only, reused for both halves)
#define NKIT   32              // KA/64 mainloop iterations

// ---------------- scratch (static device globals; no allocation) -------------
__device__ float g_q[(size_t)BH * TGT * HDIM];
__device__ float g_k[(size_t)BH * TGT * HDIM];
__device__ float g_v[(size_t)BH * TGT * HDIM];
__device__ float g_relvals[(size_t)ROWS_ALL * 512];
__device__ float g_ctx[(size_t)ROWS_ALL * EDIM];
__device__ __half g_A2[(size_t)ROWS_ALL * KA];       // [hi|lo] activations
__device__ __half g_Wqkv2[(size_t)3072 * KB];        // hi-only weights
__device__ __half g_Wrel2[(size_t)512 * KB];
__device__ __half g_Wout2[(size_t)1024 * KB];

__device__ __forceinline__ uint32_t smem_u32(const void* p) {
    uint32_t a;
    asm("{ .reg .u64 t; cvta.to.shared.u64 t, %1; cvt.u32.u64 %0, t; }" : "=r"(a) : "l"(p));
    return a;
}

// ---------------- fp16 split conversions --------------------------------------
// activations: f32 [rows][1024] -> fp16 [rows][2048] as [hi|lo]
__global__ __launch_bounds__(256)
void convert_act(const float* __restrict__ src, __half* __restrict__ dst)
{
    int i4 = (blockIdx.x * blockDim.x + threadIdx.x) * 4;
    float4 a = *(const float4*)(src + i4);
    int r = i4 >> 10, k = i4 & 1023;
    size_t base = (size_t)r * KA + k;
    float av[4] = {a.x, a.y, a.z, a.w};
    __half h[4], l[4];
#pragma unroll
    for (int j = 0; j < 4; j++) {
        h[j] = __float2half_rn(av[j]);
        l[j] = __float2half_rn(av[j] - __half2float(h[j]));
    }
    *(__half2*)(dst + base + 0) = __halves2half2(h[0], h[1]);
    *(__half2*)(dst + base + 2) = __halves2half2(h[2], h[3]);
    *(__half2*)(dst + base + 1024) = __halves2half2(l[0], l[1]);
    *(__half2*)(dst + base + 1026) = __halves2half2(l[2], l[3]);
}

// weights: f32 [N][1024] -> fp16 [N][1024] (hi only)
__global__ __launch_bounds__(256)
void convert_w(const float* __restrict__ src, __half* __restrict__ dst)
{
    int i4 = (blockIdx.x * blockDim.x + threadIdx.x) * 4;
    float4 a = *(const float4*)(src + i4);
    *(__half2*)(dst + i4 + 0) = __halves2half2(__float2half_rn(a.x), __float2half_rn(a.y));
    *(__half2*)(dst + i4 + 2) = __halves2half2(__float2half_rn(a.z), __float2half_rn(a.w));
}

// ---------------- mma.sync fp16 GEMM ------------------------------------------
// C[M,N] = A[M,2048] @ B-wrapped + bias, where B K-coord wraps mod 1024
#define GSTAGES 4
#define STAGE_BYTES 16384
#define SMEM_A 0
#define SMEM_B (GSTAGES * STAGE_BYTES)
#define GEMM_SMEM (2 * GSTAGES * STAGE_BYTES)   // 128 KB

#define LOAD_STAGE(ld) do {                                                    \
        int _s = (ld) & 3;                                                     \
        uint32_t _ab = sb + SMEM_A + _s * STAGE_BYTES;                         \
        uint32_t _bb = sb + SMEM_B + _s * STAGE_BYTES;                         \
        const __half* _ag = Ab + (ld) * 64;                                    \
        const __half* _bg = Bb + ((ld) & 15) * 64;                             \
        _Pragma("unroll")                                                      \
        for (int _c = 0; _c < 4; _c++) {                                       \
            int _chunk = tid + _c * 256;                                       \
            int _row = _chunk >> 3, _c16 = _chunk & 7;                         \
            uint32_t _off = (uint32_t)(_row * 128 + _c16 * 16);                \
            _off ^= ((_off >> 3) & 0x70);                                      \
            asm volatile("cp.async.cg.shared.global [%0], [%1], 16;"           \
                :: "r"(_ab + _off), "l"(_ag + (size_t)_row * KA + _c16 * 8));  \
            asm volatile("cp.async.cg.shared.global [%0], [%1], 16;"           \
                :: "r"(_bb + _off), "l"(_bg + (size_t)_row * KB + _c16 * 8));  \
        }                                                                      \
        asm volatile("cp.async.commit_group;");                                \
    } while (0)

#define LDSM_X4(f, addr)                                                       \
    asm volatile("ldmatrix.sync.aligned.m8n8.x4.shared.b16 {%0,%1,%2,%3}, [%4];" \
        : "=r"((f)[0]), "=r"((f)[1]), "=r"((f)[2]), "=r"((f)[3]) : "r"(addr))

#define MMA16816(d, a, b0, b1)                                                 \
    asm volatile("mma.sync.aligned.m16n8k16.row.col.f32.f16.f16.f32 "          \
        "{%0,%1,%2,%3}, {%4,%5,%6,%7}, {%8,%9}, {%0,%1,%2,%3};"                \
        : "+f"((d)[0]), "+f"((d)[1]), "+f"((d)[2]), "+f"((d)[3])               \
        : "r"((a)[0]), "r"((a)[1]), "r"((a)[2]), "r"((a)[3]),                  \
          "r"(b0), "r"(b1))

#define LOAD_FRAGS(buf, ks) do {                                               \
        _Pragma("unroll")                                                      \
        for (int _mt = 0; _mt < 2; _mt++)                                      \
            LDSM_X4(af[buf][_mt], aB + aRowByte[_mt] +                         \
                    ((uint32_t)(((ks) * 2 + achunk)) ^ xa) * 16u);             \
        _Pragma("unroll")                                                      \
        for (int _nt2 = 0; _nt2 < 4; _nt2++)                                   \
            LDSM_X4(bf[buf][_nt2], bB + bRowByte[_nt2] +                       \
                    ((uint32_t)(((ks) * 2 + bchunk)) ^ xb) * 16u);             \
    } while (0)

__global__ __launch_bounds__(256, 1)
void gemm_mma(const __half* __restrict__ A, const __half* __restrict__ B,
              const float* __restrict__ bias, float* __restrict__ C,
              int N, int qkv_mode,
              float* __restrict__ qp, float* __restrict__ kp, float* __restrict__ vp)
{
    extern __shared__ char smraw[];
    uint32_t sb = smem_u32(smraw);
    const int tid = threadIdx.x;
    const int wid = tid >> 5, lane = tid & 31;
    const int wm = wid & 3, wn = wid >> 2;       // warp tile: 32(m) x 64(n)
    const int bn = blockIdx.x, bm = blockIdx.y;
    const __half* Ab = A + (size_t)bm * 128 * KA;
    const __half* Bb = B + (size_t)bn * 128 * KB;

    float acc[2][8][4];
#pragma unroll
    for (int i = 0; i < 2; i++)
#pragma unroll
        for (int j = 0; j < 8; j++)
#pragma unroll
            for (int c = 0; c < 4; c++) acc[i][j][c] = 0.f;

    const int g = lane >> 3, r = lane & 7;
    const int rowA = wm * 32 + (g & 1) * 8 + r;
    const int achunk = (g >> 1);
    const uint32_t xa = (uint32_t)(rowA & 7);
    uint32_t aRowByte[2];
#pragma unroll
    for (int mt = 0; mt < 2; mt++) aRowByte[mt] = (uint32_t)((rowA + mt * 16) * 128);
    const int rowB = wn * 64 + (g >> 1) * 8 + r;
    const int bchunk = (g & 1);
    const uint32_t xb = (uint32_t)(rowB & 7);
    uint32_t bRowByte[4];
#pragma unroll
    for (int nt2 = 0; nt2 < 4; nt2++) bRowByte[nt2] = (uint32_t)((rowB + nt2 * 16) * 128);

    LOAD_STAGE(0); LOAD_STAGE(1); LOAD_STAGE(2);

    uint32_t af[2][2][4];
    uint32_t bf[2][4][4];

    for (int it = 0; it < NKIT; it++) {
        int pend = NKIT - 1 - it; if (pend > 2) pend = 2;
        switch (pend) {
            case 2: asm volatile("cp.async.wait_group 2;"); break;
            case 1: asm volatile("cp.async.wait_group 1;"); break;
            default: asm volatile("cp.async.wait_group 0;"); break;
        }
        __syncthreads();
        if (it + 3 < NKIT) LOAD_STAGE(it + 3);

        const uint32_t aB = sb + SMEM_A + (uint32_t)((it & 3) * STAGE_BYTES);
        const uint32_t bB = sb + SMEM_B + (uint32_t)((it & 3) * STAGE_BYTES);

        LOAD_FRAGS(0, 0);
#pragma unroll
        for (int ks = 0; ks < 4; ks++) {
            const int cur = ks & 1;
            if (ks < 3) LOAD_FRAGS(cur ^ 1, ks + 1);
#pragma unroll
            for (int mt = 0; mt < 2; mt++)
#pragma unroll
                for (int nt = 0; nt < 8; nt++) {
                    const uint32_t* bp = bf[cur][nt >> 1];
                    int o = (nt & 1) * 2;
                    MMA16816(acc[mt][nt], af[cur][mt], bp[o], bp[o + 1]);
                }
        }
    }

    // epilogue
    const int mrow0 = bm * 128 + wm * 32 + (lane >> 2);
    const int colb  = bn * 128 + wn * 64;
    if (!qkv_mode) {
#pragma unroll
        for (int mt = 0; mt < 2; mt++)
#pragma unroll
            for (int nt = 0; nt < 8; nt++) {
                int col = colb + nt * 8 + (lane & 3) * 2;
                float2 b2 = *(const float2*)&bias[col];
                int row = mrow0 + mt * 16;
                *(float2*)&C[(size_t)row * N + col] =
                    make_float2(acc[mt][nt][0] + b2.x, acc[mt][nt][1] + b2.y);
                *(float2*)&C[(size_t)(row + 8) * N + col] =
                    make_float2(acc[mt][nt][2] + b2.x, acc[mt][nt][3] + b2.y);
            }
    } else {
        const int which = colb >> 10;
        const int hh = (colb >> 6) & 15;
        float* dst = (which == 0) ? qp : (which == 1) ? kp : vp;
        const float scale = (which == 0) ? 0.125f : 1.0f;
#pragma unroll
        for (int mt = 0; mt < 2; mt++)
#pragma unroll
            for (int nt = 0; nt < 8; nt++) {
                int dd = nt * 8 + (lane & 3) * 2;
                float2 b2 = *(const float2*)&bias[colb + dd];
#pragma unroll
                for (int half = 0; half < 2; half++) {
                    int row = mrow0 + mt * 16 + half * 8;
                    int t = row >> 2, b3 = row & 3;
                    float* basep = dst + ((size_t)((b3 << 4) + hh) * TGT + t) * HDIM + dd;
                    *(float2*)basep = make_float2(
                        (acc[mt][nt][half * 2 + 0] + b2.x) * scale,
                        (acc[mt][nt][half * 2 + 1] + b2.y) * scale);
                }
            }
    }
}

// ---------------- fused flash-style attention --------------------------------
struct AttnSmem {
    float qT[64][68];
    float kT[64][68];
    float vS[64][68];
    float sS[64][68];
    float pT[64][68];
    float relrow[64][32];
    float alpha[64];
    float lrow[64];
};

__global__ __launch_bounds__(256)
void attn_kernel(const float* __restrict__ q, const float* __restrict__ k,
                 const float* __restrict__ v, const float* __restrict__ relvals,
                 const int* __restrict__ bkm, const int* __restrict__ bkn,
                 float* __restrict__ ctx)
{
    extern __shared__ char smraw[];
    AttnSmem& sm = *reinterpret_cast<AttnSmem*>(smraw);
    const int qt = blockIdx.x;
    const int bh = blockIdx.y;
    const int mode = blockIdx.z;
    const int b = bh >> 4, h = bh & 15;
    const int tid = threadIdx.x;
    const int tx = tid & 15, ty = tid >> 4;
    const int t0 = qt * 64;
    const int n = mode - 1;
    const int grow0 = mode * 512 + t0;
    const int srow = tid >> 2, spart = tid & 3;

    {
        const float* qb = q + ((size_t)bh * TGT + grow0) * HDIM;
#pragma unroll
        for (int qd = 0; qd < 4; qd++) {
            int p = tid + 256 * qd;
            int r = p >> 4;
            int dd = (p & 15) << 2;
            float4 qv = *(const float4*)(qb + r * HDIM + dd);
            sm.qT[dd + 0][r] = qv.x; sm.qT[dd + 1][r] = qv.y;
            sm.qT[dd + 2][r] = qv.z; sm.qT[dd + 3][r] = qv.w;
        }
    }
    for (int idx = tid; idx < 64 * 32; idx += 256) {
        int i = idx >> 5, nb = idx & 31;
        sm.relrow[i][nb] = relvals[((size_t)(grow0 + i) * 4 + b) * 512 + nb * 16 + h];
    }

    float m_i = -1e30f, l_i = 0.f;
    float o[4][4];
#pragma unroll
    for (int i = 0; i < 4; i++)
#pragma unroll
        for (int j = 0; j < 4; j++) o[i][j] = 0.f;

    const int nloop = (mode == 0) ? (qt + 1) : (qt + 2);
    for (int ci = 0; ci < nloop; ci++) {
        const int sc = (mode != 0 && ci == qt + 1) ? (8 + qt) : ci;
        const int s0 = sc * 64;
        const int krow0 = (sc < 8) ? s0 : (n * 512 + s0);
        __syncthreads();
        {
            const float* kb = k + ((size_t)bh * TGT + krow0) * HDIM;
            const float* vb = v + ((size_t)bh * TGT + krow0) * HDIM;
#pragma unroll
            for (int qd = 0; qd < 4; qd++) {
                int p = tid + 256 * qd;
                int r = p >> 4;
                int dd = (p & 15) << 2;
                float4 kv = *(const float4*)(kb + r * HDIM + dd);
                sm.kT[dd + 0][r] = kv.x; sm.kT[dd + 1][r] = kv.y;
                sm.kT[dd + 2][r] = kv.z; sm.kT[dd + 3][r] = kv.w;
                float4 vv = *(const float4*)(vb + r * HDIM + dd);
                *(float4*)&sm.vS[r][dd] = vv;
            }
        }
        __syncthreads();

        float sacc[4][4];
#pragma unroll
        for (int i = 0; i < 4; i++)
#pragma unroll
            for (int j = 0; j < 4; j++) sacc[i][j] = 0.f;
#pragma unroll 8
        for (int kk = 0; kk < 64; kk++) {
            float4 a  = *(float4*)&sm.qT[kk][ty * 4];
            float4 bb = *(float4*)&sm.kT[kk][tx * 4];
            float ar[4] = {a.x, a.y, a.z, a.w};
            float br[4] = {bb.x, bb.y, bb.z, bb.w};
#pragma unroll
            for (int i = 0; i < 4; i++)
#pragma unroll
                for (int j = 0; j < 4; j++) sacc[i][j] += ar[i] * br[j];
        }

#pragma unroll
        for (int ii = 0; ii < 4; ii++) {
            int i = ty * 4 + ii;
            int t_loc = t0 + i;
            int4 bk;
            if (mode == 0) bk = *(const int4*)(bkm + (size_t)t_loc * 512 + s0 + tx * 4);
            else           bk = *(const int4*)(bkn + (size_t)t_loc * 1024 + s0 + tx * 4);
            int bks[4] = {bk.x, bk.y, bk.z, bk.w};
#pragma unroll
            for (int jj = 0; jj < 4; jj++) {
                int s_g = s0 + tx * 4 + jj;
                float rel = sm.relrow[i][bks[jj]];
                bool allow;
                if (mode == 0) allow = (s_g <= t_loc);
                else allow = (s_g < 512) ? (s_g <= t_loc) : (s_g == 512 + t_loc);
                sm.sS[i][tx * 4 + jj] = sacc[ii][jj] + rel + (allow ? 0.f : -10000.f);
            }
        }
        __syncthreads();

        {
            const int i = srow;
            const int j0 = spart * 16;
            float mc = -1e30f;
#pragma unroll
            for (int j = 0; j < 16; j++) mc = fmaxf(mc, sm.sS[i][j0 + j]);
            mc = fmaxf(mc, __shfl_xor_sync(0xFFFFFFFFu, mc, 1));
            mc = fmaxf(mc, __shfl_xor_sync(0xFFFFFFFFu, mc, 2));
            float mnew = fmaxf(m_i, mc);
            float al = __expf(m_i - mnew);
            float ls = 0.f;
#pragma unroll
            for (int j = 0; j < 16; j++) {
                float e = __expf(sm.sS[i][j0 + j] - mnew);
                ls += e;
                sm.pT[j0 + j][i] = e;
            }
            ls += __shfl_xor_sync(0xFFFFFFFFu, ls, 1);
            ls += __shfl_xor_sync(0xFFFFFFFFu, ls, 2);
            l_i = l_i * al + ls;
            m_i = mnew;
            if (spart == 0) sm.alpha[i] = al;
        }
        __syncthreads();

        float alr[4];
#pragma unroll
        for (int ii = 0; ii < 4; ii++) alr[ii] = sm.alpha[ty * 4 + ii];
#pragma unroll
        for (int ii = 0; ii < 4; ii++)
#pragma unroll
            for (int jj = 0; jj < 4; jj++) o[ii][jj] *= alr[ii];
#pragma unroll 8
        for (int j = 0; j < 64; j++) {
            float4 p4 = *(float4*)&sm.pT[j][ty * 4];
            float4 v4 = *(float4*)&sm.vS[j][tx * 4];
            float pr[4] = {p4.x, p4.y, p4.z, p4.w};
            float vr[4] = {v4.x, v4.y, v4.z, v4.w};
#pragma unroll
            for (int ii = 0; ii < 4; ii++)
#pragma unroll
                for (int jj = 0; jj < 4; jj++) o[ii][jj] += pr[ii] * vr[jj];
        }
    }
    __syncthreads();
    if (spart == 0) sm.lrow[srow] = l_i;
    __syncthreads();

#pragma unroll
    for (int ii = 0; ii < 4; ii++) {
        int i = ty * 4 + ii;
        float inv = 1.0f / sm.lrow[i];
        float4 o4 = make_float4(o[ii][0] * inv, o[ii][1] * inv,
                                o[ii][2] * inv, o[ii][3] * inv);
        *(float4*)&ctx[((size_t)(grow0 + i) * 4 + b) * EDIM + h * 64 + tx * 4] = o4;
    }
}

// ---------------- launch -----------------------------------------------------
extern "C" void kernel_launch(void* const* d_in, const int* in_sizes, int n_in,
                              void* d_out, int out_size)
{
    const float* hidden = (const float*)d_in[0];
    const float* w_in   = (const float*)d_in[1];
    const float* b_in   = (const float*)d_in[2];
    const float* rel_w  = (const float*)d_in[3];
    const float* rel_b  = (const float*)d_in[4];
    const float* out_w  = (const float*)d_in[5];
    const float* out_b  = (const float*)d_in[6];
    const int* bkm = (const int*)d_in[9];
    const int* bkn = (const int*)d_in[10];
    float* out = (float*)d_out;

    float *qp, *kp, *vp, *rv, *ctx;
    __half *A2, *Wqkv2, *Wrel2, *Wout2;
    cudaGetSymbolAddress((void**)&qp,  g_q);
    cudaGetSymbolAddress((void**)&kp,  g_k);
    cudaGetSymbolAddress((void**)&vp,  g_v);
    cudaGetSymbolAddress((void**)&rv,  g_relvals);
    cudaGetSymbolAddress((void**)&ctx, g_ctx);
    cudaGetSymbolAddress((void**)&A2,    g_A2);
    cudaGetSymbolAddress((void**)&Wqkv2, g_Wqkv2);
    cudaGetSymbolAddress((void**)&Wrel2, g_Wrel2);
    cudaGetSymbolAddress((void**)&Wout2, g_Wout2);

    cudaFuncSetAttribute(gemm_mma, cudaFuncAttributeMaxDynamicSharedMemorySize, GEMM_SMEM);
    cudaFuncSetAttribute(attn_kernel, cudaFuncAttributeMaxDynamicSharedMemorySize,
                         (int)sizeof(AttnSmem));

    // 0) fp16 splits (activations [hi|lo]; weights hi-only, reused both halves)
    convert_act<<<ROWS_ALL, 256>>>(hidden, A2);
    convert_w<<<3072, 256>>>(w_in,  Wqkv2);
    convert_w<<<512,  256>>>(rel_w, Wrel2);
    convert_w<<<1024, 256>>>(out_w, Wout2);

    // 1) QKV projection (HMMA fp16, scatter into head-major q/k/v, q scaled)
    gemm_mma<<<dim3(3072 / 128, ROWS_ALL / 128), 256, GEMM_SMEM>>>(
        A2, Wqkv2, b_in, nullptr, 3072, 1, qp, kp, vp);

    // 2) rel values
    gemm_mma<<<dim3(512 / 128, ROWS_ALL / 128), 256, GEMM_SMEM>>>(
        A2, Wrel2, rel_b, rv, 512, 0, nullptr, nullptr, nullptr);

    // 3) fused attention
    attn_kernel<<<dim3(8, 64, 3), 256, sizeof(AttnSmem)>>>(qp, kp, vp, rv, bkm, bkn, ctx);

    // 4) output projection
    convert_act<<<ROWS_ALL, 256>>>(ctx, A2);
    gemm_mma<<<dim3(1024 / 128, ROWS_ALL / 128), 256, GEMM_SMEM>>>(
        A2, Wout2, out_b, out, 1024, 0, nullptr, nullptr, nullptr);
}

// round 9
// speedup vs baseline: 2.8438x; 1.2060x over previous
#include <cuda_runtime.h>
#include <cuda_fp16.h>
#include <cstdint>
#include <cstddef>

// Problem constants
#define TLEN   512
#define BATCH  4
#define HEADS  16
#define HDIM   64
#define EDIM   1024
#define ROWS_ALL 6144          // (1+NGRAM)*T * B
#define BH     64
#define TGT    1536
#define KA     2048            // activation split-K (fp16 [hi|lo])
#define KB     1024            // weight K (fp16 hi only, reused for both halves)

// ---------------- scratch (static device globals; no allocation) -------------
__device__ float g_q[(size_t)BH * TGT * HDIM];
__device__ float g_k[(size_t)BH * TGT * HDIM];
__device__ float g_v[(size_t)BH * TGT * HDIM];
__device__ float g_relvals[(size_t)ROWS_ALL * 512];
__device__ float g_ctx[(size_t)ROWS_ALL * EDIM];
__device__ __half g_A2[(size_t)ROWS_ALL * KA];       // [hi|lo] activations
__device__ __half g_Wqkv2[(size_t)3072 * KB];        // hi-only weights
__device__ __half g_Wrel2[(size_t)512 * KB];
__device__ __half g_Wout2[(size_t)1024 * KB];

__device__ __forceinline__ uint32_t smem_u32(const void* p) {
    uint32_t a;
    asm("{ .reg .u64 t; cvta.to.shared.u64 t, %1; cvt.u32.u64 %0, t; }" : "=r"(a) : "l"(p));
    return a;
}

// ---------------- fp16 split conversions --------------------------------------
__global__ __launch_bounds__(256)
void convert_act(const float* __restrict__ src, __half* __restrict__ dst)
{
    int i4 = (blockIdx.x * blockDim.x + threadIdx.x) * 4;
    float4 a = *(const float4*)(src + i4);
    int r = i4 >> 10, k = i4 & 1023;
    size_t base = (size_t)r * KA + k;
    float av[4] = {a.x, a.y, a.z, a.w};
    __half h[4], l[4];
#pragma unroll
    for (int j = 0; j < 4; j++) {
        h[j] = __float2half_rn(av[j]);
        l[j] = __float2half_rn(av[j] - __half2float(h[j]));
    }
    *(__half2*)(dst + base + 0) = __halves2half2(h[0], h[1]);
    *(__half2*)(dst + base + 2) = __halves2half2(h[2], h[3]);
    *(__half2*)(dst + base + 1024) = __halves2half2(l[0], l[1]);
    *(__half2*)(dst + base + 1026) = __halves2half2(l[2], l[3]);
}

__global__ __launch_bounds__(256)
void convert_w(const float* __restrict__ src, __half* __restrict__ dst)
{
    int i4 = (blockIdx.x * blockDim.x + threadIdx.x) * 4;
    float4 a = *(const float4*)(src + i4);
    *(__half2*)(dst + i4 + 0) = __halves2half2(__float2half_rn(a.x), __float2half_rn(a.y));
    *(__half2*)(dst + i4 + 2) = __halves2half2(__float2half_rn(a.z), __float2half_rn(a.w));
}

// ---------------- mma.sync fp16 GEMM ------------------------------------------
// C[M,N] = A[M,64*nkit] @ B(K wraps mod 1024) + bias ; 3 stages, 2 CTAs/SM
#define GSTAGES 3
#define STAGE_BYTES 16384
#define SMEM_A 0
#define SMEM_B (GSTAGES * STAGE_BYTES)
#define GEMM_SMEM (2 * GSTAGES * STAGE_BYTES)   // 96 KB

#define LOAD_STAGE(ld) do {                                                    \
        int _s = (ld) % 3;                                                     \
        uint32_t _ab = sb + SMEM_A + _s * STAGE_BYTES;                         \
        uint32_t _bb = sb + SMEM_B + _s * STAGE_BYTES;                         \
        const __half* _ag = Ab + (ld) * 64;                                    \
        const __half* _bg = Bb + ((ld) & 15) * 64;                             \
        _Pragma("unroll")                                                      \
        for (int _c = 0; _c < 4; _c++) {                                       \
            int _chunk = tid + _c * 256;                                       \
            int _row = _chunk >> 3, _c16 = _chunk & 7;                         \
            uint32_t _off = (uint32_t)(_row * 128 + _c16 * 16);                \
            _off ^= ((_off >> 3) & 0x70);                                      \
            asm volatile("cp.async.cg.shared.global [%0], [%1], 16;"           \
                :: "r"(_ab + _off), "l"(_ag + (size_t)_row * KA + _c16 * 8));  \
            asm volatile("cp.async.cg.shared.global [%0], [%1], 16;"           \
                :: "r"(_bb + _off), "l"(_bg + (size_t)_row * KB + _c16 * 8));  \
        }                                                                      \
        asm volatile("cp.async.commit_group;");                                \
    } while (0)

#define LDSM_X4(f, addr)                                                       \
    asm volatile("ldmatrix.sync.aligned.m8n8.x4.shared.b16 {%0,%1,%2,%3}, [%4];" \
        : "=r"((f)[0]), "=r"((f)[1]), "=r"((f)[2]), "=r"((f)[3]) : "r"(addr))

#define MMA16816(d, a, b0, b1)                                                 \
    asm volatile("mma.sync.aligned.m16n8k16.row.col.f32.f16.f16.f32 "          \
        "{%0,%1,%2,%3}, {%4,%5,%6,%7}, {%8,%9}, {%0,%1,%2,%3};"                \
        : "+f"((d)[0]), "+f"((d)[1]), "+f"((d)[2]), "+f"((d)[3])               \
        : "r"((a)[0]), "r"((a)[1]), "r"((a)[2]), "r"((a)[3]),                  \
          "r"(b0), "r"(b1))

#define LOAD_FRAGS(ks) do {                                                    \
        _Pragma("unroll")                                                      \
        for (int _mt = 0; _mt < 2; _mt++)                                      \
            LDSM_X4(af[_mt], aB + aRowByte[_mt] +                              \
                    ((uint32_t)(((ks) * 2 + achunk)) ^ xa) * 16u);             \
        _Pragma("unroll")                                                      \
        for (int _nt2 = 0; _nt2 < 4; _nt2++)                                   \
            LDSM_X4(bf[_nt2], bB + bRowByte[_nt2] +                            \
                    ((uint32_t)(((ks) * 2 + bchunk)) ^ xb) * 16u);             \
    } while (0)

__global__ __launch_bounds__(256, 2)
void gemm_mma(const __half* __restrict__ A, const __half* __restrict__ B,
              const float* __restrict__ bias, float* __restrict__ C,
              int N, int nkit, int qkv_mode,
              float* __restrict__ qp, float* __restrict__ kp, float* __restrict__ vp)
{
    extern __shared__ char smraw[];
    uint32_t sb = smem_u32(smraw);
    const int tid = threadIdx.x;
    const int wid = tid >> 5, lane = tid & 31;
    const int wm = wid & 3, wn = wid >> 2;       // warp tile: 32(m) x 64(n)
    const int bn = blockIdx.x, bm = blockIdx.y;
    const __half* Ab = A + (size_t)bm * 128 * KA;
    const __half* Bb = B + (size_t)bn * 128 * KB;

    float acc[2][8][4];
#pragma unroll
    for (int i = 0; i < 2; i++)
#pragma unroll
        for (int j = 0; j < 8; j++)
#pragma unroll
            for (int c = 0; c < 4; c++) acc[i][j][c] = 0.f;

    const int g = lane >> 3, r = lane & 7;
    const int rowA = wm * 32 + (g & 1) * 8 + r;
    const int achunk = (g >> 1);
    const uint32_t xa = (uint32_t)(rowA & 7);
    uint32_t aRowByte[2];
#pragma unroll
    for (int mt = 0; mt < 2; mt++) aRowByte[mt] = (uint32_t)((rowA + mt * 16) * 128);
    const int rowB = wn * 64 + (g >> 1) * 8 + r;
    const int bchunk = (g & 1);
    const uint32_t xb = (uint32_t)(rowB & 7);
    uint32_t bRowByte[4];
#pragma unroll
    for (int nt2 = 0; nt2 < 4; nt2++) bRowByte[nt2] = (uint32_t)((rowB + nt2 * 16) * 128);

    LOAD_STAGE(0); LOAD_STAGE(1);

    uint32_t af[2][4];
    uint32_t bf[4][4];

    for (int it = 0; it < nkit; it++) {
        if (it + 1 < nkit) asm volatile("cp.async.wait_group 1;");
        else               asm volatile("cp.async.wait_group 0;");
        __syncthreads();
        if (it + 2 < nkit) LOAD_STAGE(it + 2);

        const uint32_t aB = sb + SMEM_A + (uint32_t)((it % 3) * STAGE_BYTES);
        const uint32_t bB = sb + SMEM_B + (uint32_t)((it % 3) * STAGE_BYTES);
#pragma unroll
        for (int ks = 0; ks < 4; ks++) {
            LOAD_FRAGS(ks);
#pragma unroll
            for (int mt = 0; mt < 2; mt++)
#pragma unroll
                for (int nt = 0; nt < 8; nt++) {
                    const uint32_t* bp = bf[nt >> 1];
                    int o = (nt & 1) * 2;
                    MMA16816(acc[mt][nt], af[mt], bp[o], bp[o + 1]);
                }
        }
    }

    // epilogue
    const int mrow0 = bm * 128 + wm * 32 + (lane >> 2);
    const int colb  = bn * 128 + wn * 64;
    if (!qkv_mode) {
#pragma unroll
        for (int mt = 0; mt < 2; mt++)
#pragma unroll
            for (int nt = 0; nt < 8; nt++) {
                int col = colb + nt * 8 + (lane & 3) * 2;
                float2 b2 = *(const float2*)&bias[col];
                int row = mrow0 + mt * 16;
                *(float2*)&C[(size_t)row * N + col] =
                    make_float2(acc[mt][nt][0] + b2.x, acc[mt][nt][1] + b2.y);
                *(float2*)&C[(size_t)(row + 8) * N + col] =
                    make_float2(acc[mt][nt][2] + b2.x, acc[mt][nt][3] + b2.y);
            }
    } else {
        const int which = colb >> 10;
        const int hh = (colb >> 6) & 15;
        float* dst = (which == 0) ? qp : (which == 1) ? kp : vp;
        const float scale = (which == 0) ? 0.125f : 1.0f;
#pragma unroll
        for (int mt = 0; mt < 2; mt++)
#pragma unroll
            for (int nt = 0; nt < 8; nt++) {
                int dd = nt * 8 + (lane & 3) * 2;
                float2 b2 = *(const float2*)&bias[colb + dd];
#pragma unroll
                for (int half = 0; half < 2; half++) {
                    int row = mrow0 + mt * 16 + half * 8;
                    int t = row >> 2, b3 = row & 3;
                    float* basep = dst + ((size_t)((b3 << 4) + hh) * TGT + t) * HDIM + dd;
                    *(float2*)basep = make_float2(
                        (acc[mt][nt][half * 2 + 0] + b2.x) * scale,
                        (acc[mt][nt][half * 2 + 1] + b2.y) * scale);
                }
            }
    }
}

// ---------------- fused flash-style attention --------------------------------
struct AttnSmem {
    float qT[64][68];
    float kT[64][68];
    float vS[64][68];
    float sS[64][68];
    float pT[64][68];
    float relrow[64][32];
    float alpha[64];
    float pdiag[64];
    float lrow[64];
};

__global__ __launch_bounds__(256)
void attn_kernel(const float* __restrict__ q, const float* __restrict__ k,
                 const float* __restrict__ v, const float* __restrict__ relvals,
                 const int* __restrict__ bkm, const int* __restrict__ bkn,
                 float* __restrict__ ctx)
{
    extern __shared__ char smraw[];
    AttnSmem& sm = *reinterpret_cast<AttnSmem*>(smraw);
    const int qt = blockIdx.x;
    const int bh = blockIdx.y;
    const int mode = blockIdx.z;
    const int b = bh >> 4, h = bh & 15;
    const int tid = threadIdx.x;
    const int tx = tid & 15, ty = tid >> 4;
    const int t0 = qt * 64;
    const int n = mode - 1;
    const int grow0 = mode * 512 + t0;
    const int srow = tid >> 2, spart = tid & 3;

    {
        const float* qb = q + ((size_t)bh * TGT + grow0) * HDIM;
#pragma unroll
        for (int qd = 0; qd < 4; qd++) {
            int p = tid + 256 * qd;
            int r = p >> 4;
            int dd = (p & 15) << 2;
            float4 qv = *(const float4*)(qb + r * HDIM + dd);
            sm.qT[dd + 0][r] = qv.x; sm.qT[dd + 1][r] = qv.y;
            sm.qT[dd + 2][r] = qv.z; sm.qT[dd + 3][r] = qv.w;
        }
    }
    for (int idx = tid; idx < 64 * 32; idx += 256) {
        int i = idx >> 5, nb = idx & 31;
        sm.relrow[i][nb] = relvals[((size_t)(grow0 + i) * 4 + b) * 512 + nb * 16 + h];
    }

    float m_i = -1e30f, l_i = 0.f;
    float o[4][4];
#pragma unroll
    for (int i = 0; i < 4; i++)
#pragma unroll
        for (int j = 0; j < 4; j++) o[i][j] = 0.f;

    // main-range chunks only (ngram diagonal handled analytically below)
    const int nloop = qt + 1;
    for (int ci = 0; ci < nloop; ci++) {
        const int s0 = ci * 64;
        const int krow0 = s0;                // all chunks here are k_main rows
        __syncthreads();
        {
            const float* kb = k + ((size_t)bh * TGT + krow0) * HDIM;
            const float* vb = v + ((size_t)bh * TGT + krow0) * HDIM;
#pragma unroll
            for (int qd = 0; qd < 4; qd++) {
                int p = tid + 256 * qd;
                int r = p >> 4;
                int dd = (p & 15) << 2;
                float4 kv = *(const float4*)(kb + r * HDIM + dd);
                sm.kT[dd + 0][r] = kv.x; sm.kT[dd + 1][r] = kv.y;
                sm.kT[dd + 2][r] = kv.z; sm.kT[dd + 3][r] = kv.w;
                float4 vv = *(const float4*)(vb + r * HDIM + dd);
                *(float4*)&sm.vS[r][dd] = vv;
            }
        }
        __syncthreads();

        float sacc[4][4];
#pragma unroll
        for (int i = 0; i < 4; i++)
#pragma unroll
            for (int j = 0; j < 4; j++) sacc[i][j] = 0.f;
#pragma unroll 8
        for (int kk = 0; kk < 64; kk++) {
            float4 a  = *(float4*)&sm.qT[kk][ty * 4];
            float4 bb = *(float4*)&sm.kT[kk][tx * 4];
            float ar[4] = {a.x, a.y, a.z, a.w};
            float br[4] = {bb.x, bb.y, bb.z, bb.w};
#pragma unroll
            for (int i = 0; i < 4; i++)
#pragma unroll
                for (int j = 0; j < 4; j++) sacc[i][j] += ar[i] * br[j];
        }

#pragma unroll
        for (int ii = 0; ii < 4; ii++) {
            int i = ty * 4 + ii;
            int t_loc = t0 + i;
            int4 bk;
            if (mode == 0) bk = *(const int4*)(bkm + (size_t)t_loc * 512 + s0 + tx * 4);
            else           bk = *(const int4*)(bkn + (size_t)t_loc * 1024 + s0 + tx * 4);
            int bks[4] = {bk.x, bk.y, bk.z, bk.w};
#pragma unroll
            for (int jj = 0; jj < 4; jj++) {
                int s_g = s0 + tx * 4 + jj;
                float rel = sm.relrow[i][bks[jj]];
                bool allow = (s_g <= t_loc);   // main-range mask (same for all modes)
                sm.sS[i][tx * 4 + jj] = sacc[ii][jj] + rel + (allow ? 0.f : -10000.f);
            }
        }
        __syncthreads();

        {
            const int i = srow;
            const int j0 = spart * 16;
            float mc = -1e30f;
#pragma unroll
            for (int j = 0; j < 16; j++) mc = fmaxf(mc, sm.sS[i][j0 + j]);
            mc = fmaxf(mc, __shfl_xor_sync(0xFFFFFFFFu, mc, 1));
            mc = fmaxf(mc, __shfl_xor_sync(0xFFFFFFFFu, mc, 2));
            float mnew = fmaxf(m_i, mc);
            float al = __expf(m_i - mnew);
            float ls = 0.f;
#pragma unroll
            for (int j = 0; j < 16; j++) {
                float e = __expf(sm.sS[i][j0 + j] - mnew);
                ls += e;
                sm.pT[j0 + j][i] = e;
            }
            ls += __shfl_xor_sync(0xFFFFFFFFu, ls, 1);
            ls += __shfl_xor_sync(0xFFFFFFFFu, ls, 2);
            l_i = l_i * al + ls;
            m_i = mnew;
            if (spart == 0) sm.alpha[i] = al;
        }
        __syncthreads();

        float alr[4];
#pragma unroll
        for (int ii = 0; ii < 4; ii++) alr[ii] = sm.alpha[ty * 4 + ii];
#pragma unroll
        for (int ii = 0; ii < 4; ii++)
#pragma unroll
            for (int jj = 0; jj < 4; jj++) o[ii][jj] *= alr[ii];
#pragma unroll 8
        for (int j = 0; j < 64; j++) {
            float4 p4 = *(float4*)&sm.pT[j][ty * 4];
            float4 v4 = *(float4*)&sm.vS[j][tx * 4];
            float pr[4] = {p4.x, p4.y, p4.z, p4.w};
            float vr[4] = {v4.x, v4.y, v4.z, v4.w};
#pragma unroll
            for (int ii = 0; ii < 4; ii++)
#pragma unroll
                for (int jj = 0; jj < 4; jj++) o[ii][jj] += pr[ii] * vr[jj];
        }
    }

    // analytic ngram diagonal: single allowed key s == 512 + t
    if (mode != 0) {
        __syncthreads();   // protect alpha/pdiag against stragglers of last chunk
        {
            const int t_loc = t0 + srow;
            const int krow = n * 512 + 512 + t_loc;
            const float* kr = k + ((size_t)bh * TGT + krow) * HDIM + spart * 16;
            float dot = 0.f;
#pragma unroll
            for (int j = 0; j < 16; j++) dot += sm.qT[spart * 16 + j][srow] * kr[j];
            dot += __shfl_xor_sync(0xFFFFFFFFu, dot, 1);
            dot += __shfl_xor_sync(0xFFFFFFFFu, dot, 2);
            int bk = bkn[(size_t)t_loc * 1024 + 512 + t_loc];
            float L = dot + sm.relrow[srow][bk];
            float mnew = fmaxf(m_i, L);
            float al = __expf(m_i - mnew);
            float p = __expf(L - mnew);
            l_i = l_i * al + p;
            m_i = mnew;
            if (spart == 0) { sm.alpha[srow] = al; sm.pdiag[srow] = p; }
        }
        __syncthreads();
#pragma unroll
        for (int ii = 0; ii < 4; ii++) {
            int i = ty * 4 + ii;
            int krow = n * 512 + 512 + t0 + i;
            const float* vr = v + ((size_t)bh * TGT + krow) * HDIM + tx * 4;
            float al2 = sm.alpha[i], p2 = sm.pdiag[i];
            float4 v4 = *(const float4*)vr;
            o[ii][0] = o[ii][0] * al2 + p2 * v4.x;
            o[ii][1] = o[ii][1] * al2 + p2 * v4.y;
            o[ii][2] = o[ii][2] * al2 + p2 * v4.z;
            o[ii][3] = o[ii][3] * al2 + p2 * v4.w;
        }
    }

    __syncthreads();
    if (spart == 0) sm.lrow[srow] = l_i;
    __syncthreads();

#pragma unroll
    for (int ii = 0; ii < 4; ii++) {
        int i = ty * 4 + ii;
        float inv = 1.0f / sm.lrow[i];
        float4 o4 = make_float4(o[ii][0] * inv, o[ii][1] * inv,
                                o[ii][2] * inv, o[ii][3] * inv);
        *(float4*)&ctx[((size_t)(grow0 + i) * 4 + b) * EDIM + h * 64 + tx * 4] = o4;
    }
}

// ---------------- launch -----------------------------------------------------
extern "C" void kernel_launch(void* const* d_in, const int* in_sizes, int n_in,
                              void* d_out, int out_size)
{
    const float* hidden = (const float*)d_in[0];
    const float* w_in   = (const float*)d_in[1];
    const float* b_in   = (const float*)d_in[2];
    const float* rel_w  = (const float*)d_in[3];
    const float* rel_b  = (const float*)d_in[4];
    const float* out_w  = (const float*)d_in[5];
    const float* out_b  = (const float*)d_in[6];
    const int* bkm = (const int*)d_in[9];
    const int* bkn = (const int*)d_in[10];
    float* out = (float*)d_out;

    float *qp, *kp, *vp, *rv, *ctx;
    __half *A2, *Wqkv2, *Wrel2, *Wout2;
    cudaGetSymbolAddress((void**)&qp,  g_q);
    cudaGetSymbolAddress((void**)&kp,  g_k);
    cudaGetSymbolAddress((void**)&vp,  g_v);
    cudaGetSymbolAddress((void**)&rv,  g_relvals);
    cudaGetSymbolAddress((void**)&ctx, g_ctx);
    cudaGetSymbolAddress((void**)&A2,    g_A2);
    cudaGetSymbolAddress((void**)&Wqkv2, g_Wqkv2);
    cudaGetSymbolAddress((void**)&Wrel2, g_Wrel2);
    cudaGetSymbolAddress((void**)&Wout2, g_Wout2);

    cudaFuncSetAttribute(gemm_mma, cudaFuncAttributeMaxDynamicSharedMemorySize, GEMM_SMEM);
    cudaFuncSetAttribute(attn_kernel, cudaFuncAttributeMaxDynamicSharedMemorySize,
                         (int)sizeof(AttnSmem));

    // 0) fp16 splits (activations [hi|lo]; weights hi-only)
    convert_act<<<ROWS_ALL, 256>>>(hidden, A2);
    convert_w<<<3072, 256>>>(w_in,  Wqkv2);
    convert_w<<<512,  256>>>(rel_w, Wrel2);
    convert_w<<<1024, 256>>>(out_w, Wout2);

    // 1) QKV projection (fp16 2-term, K=2048)
    gemm_mma<<<dim3(3072 / 128, ROWS_ALL / 128), 256, GEMM_SMEM>>>(
        A2, Wqkv2, b_in, nullptr, 3072, 32, 1, qp, kp, vp);

    // 2) rel values (hi-only, K=1024 — additive-to-logits term tolerates it)
    gemm_mma<<<dim3(512 / 128, ROWS_ALL / 128), 256, GEMM_SMEM>>>(
        A2, Wrel2, rel_b, rv, 512, 16, 0, nullptr, nullptr, nullptr);

    // 3) fused attention (analytic ngram diagonal)
    attn_kernel<<<dim3(8, 64, 3), 256, sizeof(AttnSmem)>>>(qp, kp, vp, rv, bkm, bkn, ctx);

    // 4) output projection (fp16 2-term, K=2048)
    convert_act<<<ROWS_ALL, 256>>>(ctx, A2);
    gemm_mma<<<dim3(1024 / 128, ROWS_ALL / 128), 256, GEMM_SMEM>>>(
        A2, Wout2, out_b, out, 1024, 32, 0, nullptr, nullptr, nullptr);
}

// round 10
// speedup vs baseline: 3.9685x; 1.3955x over previous
#include <cuda_runtime.h>
#include <cuda_fp16.h>
#include <cstdint>
#include <cstddef>

// Problem constants
#define TLEN   512
#define BATCH  4
#define HEADS  16
#define HDIM   64
#define EDIM   1024
#define ROWS_ALL 6144          // (1+NGRAM)*T * B
#define BH     64
#define TGT    1536
#define KA     2048            // activation split-K (fp16 [hi|lo])
#define KB     1024            // weight K (fp16 hi only, reused for both halves)

// ---------------- scratch (static device globals; no allocation) -------------
__device__ float g_q[(size_t)BH * TGT * HDIM];
__device__ float g_k[(size_t)BH * TGT * HDIM];
__device__ float g_v[(size_t)BH * TGT * HDIM];
__device__ float g_relvals[(size_t)ROWS_ALL * 512];
__device__ float g_ctx[(size_t)ROWS_ALL * EDIM];
__device__ __half g_A2[(size_t)ROWS_ALL * KA];       // [hi|lo] activations
__device__ __half g_Wqkv2[(size_t)3072 * KB];        // hi-only weights
__device__ __half g_Wrel2[(size_t)512 * KB];
__device__ __half g_Wout2[(size_t)1024 * KB];

__device__ __forceinline__ uint32_t smem_u32(const void* p) {
    uint32_t a;
    asm("{ .reg .u64 t; cvta.to.shared.u64 t, %1; cvt.u32.u64 %0, t; }" : "=r"(a) : "l"(p));
    return a;
}
__device__ __forceinline__ uint32_t pack_h2(__half a, __half b) {
    __half2 t = __halves2half2(a, b);
    return *reinterpret_cast<uint32_t*>(&t);
}

// ---------------- fp16 split conversions --------------------------------------
__global__ __launch_bounds__(256)
void convert_act(const float* __restrict__ src, __half* __restrict__ dst)
{
    int i4 = (blockIdx.x * blockDim.x + threadIdx.x) * 4;
    float4 a = *(const float4*)(src + i4);
    int r = i4 >> 10, k = i4 & 1023;
    size_t base = (size_t)r * KA + k;
    float av[4] = {a.x, a.y, a.z, a.w};
    __half h[4], l[4];
#pragma unroll
    for (int j = 0; j < 4; j++) {
        h[j] = __float2half_rn(av[j]);
        l[j] = __float2half_rn(av[j] - __half2float(h[j]));
    }
    *(__half2*)(dst + base + 0) = __halves2half2(h[0], h[1]);
    *(__half2*)(dst + base + 2) = __halves2half2(h[2], h[3]);
    *(__half2*)(dst + base + 1024) = __halves2half2(l[0], l[1]);
    *(__half2*)(dst + base + 1026) = __halves2half2(l[2], l[3]);
}

__global__ __launch_bounds__(256)
void convert_w(const float* __restrict__ src, __half* __restrict__ dst)
{
    int i4 = (blockIdx.x * blockDim.x + threadIdx.x) * 4;
    float4 a = *(const float4*)(src + i4);
    *(__half2*)(dst + i4 + 0) = __halves2half2(__float2half_rn(a.x), __float2half_rn(a.y));
    *(__half2*)(dst + i4 + 2) = __halves2half2(__float2half_rn(a.z), __float2half_rn(a.w));
}

// ---------------- mma.sync fp16 GEMM (unchanged, committed) -------------------
#define GSTAGES 3
#define STAGE_BYTES 16384
#define SMEM_A 0
#define SMEM_B (GSTAGES * STAGE_BYTES)
#define GEMM_SMEM (2 * GSTAGES * STAGE_BYTES)   // 96 KB

#define LOAD_STAGE(ld) do {                                                    \
        int _s = (ld) % 3;                                                     \
        uint32_t _ab = sb + SMEM_A + _s * STAGE_BYTES;                         \
        uint32_t _bb = sb + SMEM_B + _s * STAGE_BYTES;                         \
        const __half* _ag = Ab + (ld) * 64;                                    \
        const __half* _bg = Bb + ((ld) & 15) * 64;                             \
        _Pragma("unroll")                                                      \
        for (int _c = 0; _c < 4; _c++) {                                       \
            int _chunk = tid + _c * 256;                                       \
            int _row = _chunk >> 3, _c16 = _chunk & 7;                         \
            uint32_t _off = (uint32_t)(_row * 128 + _c16 * 16);                \
            _off ^= ((_off >> 3) & 0x70);                                      \
            asm volatile("cp.async.cg.shared.global [%0], [%1], 16;"           \
                :: "r"(_ab + _off), "l"(_ag + (size_t)_row * KA + _c16 * 8));  \
            asm volatile("cp.async.cg.shared.global [%0], [%1], 16;"           \
                :: "r"(_bb + _off), "l"(_bg + (size_t)_row * KB + _c16 * 8));  \
        }                                                                      \
        asm volatile("cp.async.commit_group;");                                \
    } while (0)

#define LDSM_X4(f, addr)                                                       \
    asm volatile("ldmatrix.sync.aligned.m8n8.x4.shared.b16 {%0,%1,%2,%3}, [%4];" \
        : "=r"((f)[0]), "=r"((f)[1]), "=r"((f)[2]), "=r"((f)[3]) : "r"(addr))

#define LDSM_X4T(f, addr)                                                      \
    asm volatile("ldmatrix.sync.aligned.m8n8.x4.trans.shared.b16 {%0,%1,%2,%3}, [%4];" \
        : "=r"((f)[0]), "=r"((f)[1]), "=r"((f)[2]), "=r"((f)[3]) : "r"(addr))

#define MMA16816(d, a, b0, b1)                                                 \
    asm volatile("mma.sync.aligned.m16n8k16.row.col.f32.f16.f16.f32 "          \
        "{%0,%1,%2,%3}, {%4,%5,%6,%7}, {%8,%9}, {%0,%1,%2,%3};"                \
        : "+f"((d)[0]), "+f"((d)[1]), "+f"((d)[2]), "+f"((d)[3])               \
        : "r"((a)[0]), "r"((a)[1]), "r"((a)[2]), "r"((a)[3]),                  \
          "r"(b0), "r"(b1))

#define LOAD_FRAGS(ks) do {                                                    \
        _Pragma("unroll")                                                      \
        for (int _mt = 0; _mt < 2; _mt++)                                      \
            LDSM_X4(af[_mt], aB + aRowByte[_mt] +                              \
                    ((uint32_t)(((ks) * 2 + achunk)) ^ xa) * 16u);             \
        _Pragma("unroll")                                                      \
        for (int _nt2 = 0; _nt2 < 4; _nt2++)                                   \
            LDSM_X4(bf[_nt2], bB + bRowByte[_nt2] +                            \
                    ((uint32_t)(((ks) * 2 + bchunk)) ^ xb) * 16u);             \
    } while (0)

__global__ __launch_bounds__(256, 2)
void gemm_mma(const __half* __restrict__ A, const __half* __restrict__ B,
              const float* __restrict__ bias, float* __restrict__ C,
              int N, int nkit, int qkv_mode,
              float* __restrict__ qp, float* __restrict__ kp, float* __restrict__ vp)
{
    extern __shared__ char smraw[];
    uint32_t sb = smem_u32(smraw);
    const int tid = threadIdx.x;
    const int wid = tid >> 5, lane = tid & 31;
    const int wm = wid & 3, wn = wid >> 2;
    const int bn = blockIdx.x, bm = blockIdx.y;
    const __half* Ab = A + (size_t)bm * 128 * KA;
    const __half* Bb = B + (size_t)bn * 128 * KB;

    float acc[2][8][4];
#pragma unroll
    for (int i = 0; i < 2; i++)
#pragma unroll
        for (int j = 0; j < 8; j++)
#pragma unroll
            for (int c = 0; c < 4; c++) acc[i][j][c] = 0.f;

    const int g = lane >> 3, r = lane & 7;
    const int rowA = wm * 32 + (g & 1) * 8 + r;
    const int achunk = (g >> 1);
    const uint32_t xa = (uint32_t)(rowA & 7);
    uint32_t aRowByte[2];
#pragma unroll
    for (int mt = 0; mt < 2; mt++) aRowByte[mt] = (uint32_t)((rowA + mt * 16) * 128);
    const int rowB = wn * 64 + (g >> 1) * 8 + r;
    const int bchunk = (g & 1);
    const uint32_t xb = (uint32_t)(rowB & 7);
    uint32_t bRowByte[4];
#pragma unroll
    for (int nt2 = 0; nt2 < 4; nt2++) bRowByte[nt2] = (uint32_t)((rowB + nt2 * 16) * 128);

    LOAD_STAGE(0); LOAD_STAGE(1);

    uint32_t af[2][4];
    uint32_t bf[4][4];

    for (int it = 0; it < nkit; it++) {
        if (it + 1 < nkit) asm volatile("cp.async.wait_group 1;");
        else               asm volatile("cp.async.wait_group 0;");
        __syncthreads();
        if (it + 2 < nkit) LOAD_STAGE(it + 2);

        const uint32_t aB = sb + SMEM_A + (uint32_t)((it % 3) * STAGE_BYTES);
        const uint32_t bB = sb + SMEM_B + (uint32_t)((it % 3) * STAGE_BYTES);
#pragma unroll
        for (int ks = 0; ks < 4; ks++) {
            LOAD_FRAGS(ks);
#pragma unroll
            for (int mt = 0; mt < 2; mt++)
#pragma unroll
                for (int nt = 0; nt < 8; nt++) {
                    const uint32_t* bp = bf[nt >> 1];
                    int o = (nt & 1) * 2;
                    MMA16816(acc[mt][nt], af[mt], bp[o], bp[o + 1]);
                }
        }
    }

    const int mrow0 = bm * 128 + wm * 32 + (lane >> 2);
    const int colb  = bn * 128 + wn * 64;
    if (!qkv_mode) {
#pragma unroll
        for (int mt = 0; mt < 2; mt++)
#pragma unroll
            for (int nt = 0; nt < 8; nt++) {
                int col = colb + nt * 8 + (lane & 3) * 2;
                float2 b2 = *(const float2*)&bias[col];
                int row = mrow0 + mt * 16;
                *(float2*)&C[(size_t)row * N + col] =
                    make_float2(acc[mt][nt][0] + b2.x, acc[mt][nt][1] + b2.y);
                *(float2*)&C[(size_t)(row + 8) * N + col] =
                    make_float2(acc[mt][nt][2] + b2.x, acc[mt][nt][3] + b2.y);
            }
    } else {
        const int which = colb >> 10;
        const int hh = (colb >> 6) & 15;
        float* dst = (which == 0) ? qp : (which == 1) ? kp : vp;
        const float scale = (which == 0) ? 0.125f : 1.0f;
#pragma unroll
        for (int mt = 0; mt < 2; mt++)
#pragma unroll
            for (int nt = 0; nt < 8; nt++) {
                int dd = nt * 8 + (lane & 3) * 2;
                float2 b2 = *(const float2*)&bias[colb + dd];
#pragma unroll
                for (int half = 0; half < 2; half++) {
                    int row = mrow0 + mt * 16 + half * 8;
                    int t = row >> 2, b3 = row & 3;
                    float* basep = dst + ((size_t)((b3 << 4) + hh) * TGT + t) * HDIM + dd;
                    *(float2*)basep = make_float2(
                        (acc[mt][nt][half * 2 + 0] + b2.x) * scale,
                        (acc[mt][nt][half * 2 + 1] + b2.y) * scale);
                }
            }
    }
}

// ---------------- tensor-core flash attention ---------------------------------
// block: 128 threads (4 warps); warp w owns q-rows w*16..w*16+15.
// fp16 planes [64][64], 128B rows, swizzle: chunk16 ^= (row&7).
struct AttnTc {
    __half qh[4096];
    __half ql[4096];
    __half kh[4096];
    __half vh[4096];        // v row-major [s][d] (hi); B frags via ldmatrix.trans
    float relrow[64][32];
    float Ld[64];
};

__global__ __launch_bounds__(128)
void attn_tc(const float* __restrict__ q, const float* __restrict__ k,
             const float* __restrict__ v, const float* __restrict__ relvals,
             const int* __restrict__ bkm, const int* __restrict__ bkn,
             float* __restrict__ ctx)
{
    extern __shared__ char smraw[];
    AttnTc& sm = *reinterpret_cast<AttnTc*>(smraw);
    const int qt = blockIdx.x, bh = blockIdx.y, mode = blockIdx.z;
    const int b = bh >> 4, h = bh & 15;
    const int tid = threadIdx.x, wid = tid >> 5, lane = tid & 31;
    const int t0 = qt * 64, n = mode - 1, grow0 = mode * 512 + t0;
    const int qr = lane >> 2, qc = lane & 3;         // quad row / col group
    const int g = lane >> 3, r8 = lane & 7;

    // ---- load Q (split into hi/lo planes) and relrow ----
    const float* qb = q + ((size_t)bh * TGT + grow0) * HDIM;
    for (int i = tid; i < 512; i += 128) {
        int row = i >> 3, c = i & 7;
        const float* src = qb + row * 64 + c * 8;
        float4 x0 = *(const float4*)src, x1 = *(const float4*)(src + 4);
        float xs[8] = {x0.x, x0.y, x0.z, x0.w, x1.x, x1.y, x1.z, x1.w};
        __half hh[8], ll[8];
#pragma unroll
        for (int j = 0; j < 8; j++) {
            hh[j] = __float2half_rn(xs[j]);
            ll[j] = __float2half_rn(xs[j] - __half2float(hh[j]));
        }
        int idx = row * 64 + ((c ^ (row & 7)) << 3);
        uint4 hv, lv;
        hv.x = pack_h2(hh[0], hh[1]); hv.y = pack_h2(hh[2], hh[3]);
        hv.z = pack_h2(hh[4], hh[5]); hv.w = pack_h2(hh[6], hh[7]);
        lv.x = pack_h2(ll[0], ll[1]); lv.y = pack_h2(ll[2], ll[3]);
        lv.z = pack_h2(ll[4], ll[5]); lv.w = pack_h2(ll[6], ll[7]);
        *(uint4*)&sm.qh[idx] = hv;
        *(uint4*)&sm.ql[idx] = lv;
    }
    for (int idx = tid; idx < 2048; idx += 128) {
        int i = idx >> 5, nb = idx & 31;
        sm.relrow[i][nb] = relvals[((size_t)(grow0 + i) * 4 + b) * 512 + nb * 16 + h];
    }
    __syncthreads();

    // ---- hoist Q fragments into registers (all chunks reuse) ----
    const uint32_t qh_base = smem_u32(sm.qh), ql_base = smem_u32(sm.ql);
    const uint32_t kh_base = smem_u32(sm.kh), vh_base = smem_u32(sm.vh);
    const int arow = wid * 16 + (g & 1) * 8 + r8;
    const int achunk = g >> 1;
    uint32_t afh[4][4], afl[4][4];
#pragma unroll
    for (int ks = 0; ks < 4; ks++) {
        uint32_t off = (uint32_t)(arow * 128 + (((ks * 2 + achunk) ^ (arow & 7)) * 16));
        LDSM_X4(afh[ks], qh_base + off);
        LDSM_X4(afl[ks], ql_base + off);
    }

    // B-lane mapping for QK (keys, K-contiguous) and PV (v trans)
    const int brow8 = (g >> 1) * 8 + r8;     // QK: row-within-16 group
    const int bchunk = g & 1;
    const int vrow8 = (g & 1) * 8 + r8;      // PV: s-row-within-16 group
    const int vdo = g >> 1;                  // PV: d-chunk offset

    float m_i[2] = {-1e30f, -1e30f}, l_i[2] = {0.f, 0.f};
    float of[8][4];
#pragma unroll
    for (int nt = 0; nt < 8; nt++)
#pragma unroll
        for (int c = 0; c < 4; c++) of[nt][c] = 0.f;

    const int nloop = qt + 1;
    const int bstride = (mode == 0) ? 512 : 1024;
    const int* bkp = (mode == 0) ? bkm : bkn;

    for (int ci = 0; ci < nloop; ci++) {
        const int s0 = ci * 64;
        __syncthreads();
        // load K,V chunk (fp16 hi planes)
        {
            const float* kb = k + ((size_t)bh * TGT + s0) * HDIM;
            const float* vb = v + ((size_t)bh * TGT + s0) * HDIM;
            for (int i = tid; i < 512; i += 128) {
                int row = i >> 3, c = i & 7;
                int idx = row * 64 + ((c ^ (row & 7)) << 3);
                const float* ks_ = kb + row * 64 + c * 8;
                float4 a0 = *(const float4*)ks_, a1 = *(const float4*)(ks_ + 4);
                uint4 kv;
                kv.x = pack_h2(__float2half_rn(a0.x), __float2half_rn(a0.y));
                kv.y = pack_h2(__float2half_rn(a0.z), __float2half_rn(a0.w));
                kv.z = pack_h2(__float2half_rn(a1.x), __float2half_rn(a1.y));
                kv.w = pack_h2(__float2half_rn(a1.z), __float2half_rn(a1.w));
                *(uint4*)&sm.kh[idx] = kv;
                const float* vs_ = vb + row * 64 + c * 8;
                float4 b0 = *(const float4*)vs_, b1 = *(const float4*)(vs_ + 4);
                uint4 vv;
                vv.x = pack_h2(__float2half_rn(b0.x), __float2half_rn(b0.y));
                vv.y = pack_h2(__float2half_rn(b0.z), __float2half_rn(b0.w));
                vv.z = pack_h2(__float2half_rn(b1.x), __float2half_rn(b1.y));
                vv.w = pack_h2(__float2half_rn(b1.z), __float2half_rn(b1.w));
                *(uint4*)&sm.vh[idx] = vv;
            }
        }
        __syncthreads();

        // ---- S = [qhi|qlo] @ [khi|khi]^T ----
        float sacc[8][4];
#pragma unroll
        for (int nt = 0; nt < 8; nt++)
#pragma unroll
            for (int c = 0; c < 4; c++) sacc[nt][c] = 0.f;
#pragma unroll
        for (int ks = 0; ks < 4; ks++) {
            uint32_t bq[4][4];
#pragma unroll
            for (int nt2 = 0; nt2 < 4; nt2++) {
                int krow = nt2 * 16 + brow8;
                uint32_t off = (uint32_t)(krow * 128 + (((ks * 2 + bchunk) ^ (krow & 7)) * 16));
                LDSM_X4(bq[nt2], kh_base + off);
            }
#pragma unroll
            for (int nt2 = 0; nt2 < 4; nt2++) {
                MMA16816(sacc[2 * nt2],     afh[ks], bq[nt2][0], bq[nt2][1]);
                MMA16816(sacc[2 * nt2 + 1], afh[ks], bq[nt2][2], bq[nt2][3]);
                MMA16816(sacc[2 * nt2],     afl[ks], bq[nt2][0], bq[nt2][1]);
                MMA16816(sacc[2 * nt2 + 1], afl[ks], bq[nt2][2], bq[nt2][3]);
            }
        }

        // ---- rel + mask ----
#pragma unroll
        for (int rh = 0; rh < 2; rh++) {
            int rl = wid * 16 + qr + rh * 8;
            int t_loc = t0 + rl;
            const int* bkrow = bkp + (size_t)t_loc * bstride + s0 + qc * 2;
#pragma unroll
            for (int nt = 0; nt < 8; nt++) {
                int2 bk2 = *(const int2*)(bkrow + nt * 8);
                int sg = s0 + nt * 8 + qc * 2;
                sacc[nt][rh * 2 + 0] += sm.relrow[rl][bk2.x] + ((sg     <= t_loc) ? 0.f : -10000.f);
                sacc[nt][rh * 2 + 1] += sm.relrow[rl][bk2.y] + ((sg + 1 <= t_loc) ? 0.f : -10000.f);
            }
        }

        // ---- online softmax (registers + quad shuffles) ----
#pragma unroll
        for (int rh = 0; rh < 2; rh++) {
            float mc = -1e30f;
#pragma unroll
            for (int nt = 0; nt < 8; nt++) {
                mc = fmaxf(mc, sacc[nt][rh * 2]);
                mc = fmaxf(mc, sacc[nt][rh * 2 + 1]);
            }
            mc = fmaxf(mc, __shfl_xor_sync(0xFFFFFFFFu, mc, 1));
            mc = fmaxf(mc, __shfl_xor_sync(0xFFFFFFFFu, mc, 2));
            float mnew = fmaxf(m_i[rh], mc);
            float al = __expf(m_i[rh] - mnew);
            float ls = 0.f;
#pragma unroll
            for (int nt = 0; nt < 8; nt++) {
                float e0 = __expf(sacc[nt][rh * 2]     - mnew);
                float e1 = __expf(sacc[nt][rh * 2 + 1] - mnew);
                sacc[nt][rh * 2] = e0; sacc[nt][rh * 2 + 1] = e1;
                ls += e0 + e1;
            }
            ls += __shfl_xor_sync(0xFFFFFFFFu, ls, 1);
            ls += __shfl_xor_sync(0xFFFFFFFFu, ls, 2);
            l_i[rh] = l_i[rh] * al + ls;
            m_i[rh] = mnew;
#pragma unroll
            for (int nt = 0; nt < 8; nt++) {
                of[nt][rh * 2] *= al; of[nt][rh * 2 + 1] *= al;
            }
        }

        // ---- O += [Phi|Plo] @ [vhi|vhi] ----
#pragma unroll
        for (int ks = 0; ks < 4; ks++) {
            uint32_t bv[4][4];
#pragma unroll
            for (int nt2 = 0; nt2 < 4; nt2++) {
                int srow = ks * 16 + vrow8;
                int dchunk = nt2 * 2 + vdo;
                uint32_t off = (uint32_t)(srow * 128 + ((dchunk ^ (srow & 7)) * 16));
                LDSM_X4T(bv[nt2], vh_base + off);
            }
            // P fragments for this s16 block: S tiles 2ks, 2ks+1
            uint32_t ph[4], pl[4];
            {
                float e[8] = {sacc[2*ks][0], sacc[2*ks][1], sacc[2*ks][2], sacc[2*ks][3],
                              sacc[2*ks+1][0], sacc[2*ks+1][1], sacc[2*ks+1][2], sacc[2*ks+1][3]};
                __half eh[8], el[8];
#pragma unroll
                for (int j = 0; j < 8; j++) {
                    eh[j] = __float2half_rn(e[j]);
                    el[j] = __float2half_rn(e[j] - __half2float(eh[j]));
                }
                ph[0] = pack_h2(eh[0], eh[1]); ph[1] = pack_h2(eh[2], eh[3]);
                ph[2] = pack_h2(eh[4], eh[5]); ph[3] = pack_h2(eh[6], eh[7]);
                pl[0] = pack_h2(el[0], el[1]); pl[1] = pack_h2(el[2], el[3]);
                pl[2] = pack_h2(el[4], el[5]); pl[3] = pack_h2(el[6], el[7]);
            }
#pragma unroll
            for (int nt2 = 0; nt2 < 4; nt2++) {
                MMA16816(of[2 * nt2],     ph, bv[nt2][0], bv[nt2][1]);
                MMA16816(of[2 * nt2 + 1], ph, bv[nt2][2], bv[nt2][3]);
                MMA16816(of[2 * nt2],     pl, bv[nt2][0], bv[nt2][1]);
                MMA16816(of[2 * nt2 + 1], pl, bv[nt2][2], bv[nt2][3]);
            }
        }
    }

    // ---- analytic ngram diagonal (single key s == 512 + t) ----
    if (mode != 0) {
        {
            int row = tid >> 1, hf = tid & 1;
            int t_loc = t0 + row;
            int krow = n * 512 + 512 + t_loc;
            const float* kr = k + ((size_t)bh * TGT + krow) * HDIM + hf * 32;
            const float* qr2 = qb + row * 64 + hf * 32;
            float dot = 0.f;
#pragma unroll
            for (int j = 0; j < 8; j++) {
                float4 qa = *(const float4*)(qr2 + j * 4);
                float4 ka = *(const float4*)(kr + j * 4);
                dot += qa.x * ka.x + qa.y * ka.y + qa.z * ka.z + qa.w * ka.w;
            }
            dot += __shfl_xor_sync(0xFFFFFFFFu, dot, 1);
            int bk = bkn[(size_t)t_loc * 1024 + 512 + t_loc];
            float L = dot + sm.relrow[row][bk];
            if (!hf) sm.Ld[row] = L;
        }
        __syncthreads();
#pragma unroll
        for (int rh = 0; rh < 2; rh++) {
            int rl = wid * 16 + qr + rh * 8;
            int t_loc = t0 + rl;
            float L = sm.Ld[rl];
            float mnew = fmaxf(m_i[rh], L);
            float al = __expf(m_i[rh] - mnew);
            float p = __expf(L - mnew);
            l_i[rh] = l_i[rh] * al + p;
            m_i[rh] = mnew;
            const float* vr = v + ((size_t)bh * TGT + n * 512 + 512 + t_loc) * HDIM + qc * 2;
#pragma unroll
            for (int nt = 0; nt < 8; nt++) {
                float2 v2 = *(const float2*)(vr + nt * 8);
                of[nt][rh * 2]     = of[nt][rh * 2]     * al + p * v2.x;
                of[nt][rh * 2 + 1] = of[nt][rh * 2 + 1] * al + p * v2.y;
            }
        }
    }

    // ---- epilogue: normalize + write ctx ----
#pragma unroll
    for (int rh = 0; rh < 2; rh++) {
        int rl = wid * 16 + qr + rh * 8;
        float inv = 1.0f / l_i[rh];
        float* cb = ctx + ((size_t)(grow0 + rl) * 4 + b) * EDIM + h * 64 + qc * 2;
#pragma unroll
        for (int nt = 0; nt < 8; nt++)
            *(float2*)(cb + nt * 8) = make_float2(of[nt][rh * 2] * inv,
                                                  of[nt][rh * 2 + 1] * inv);
    }
}

// ---------------- launch -----------------------------------------------------
extern "C" void kernel_launch(void* const* d_in, const int* in_sizes, int n_in,
                              void* d_out, int out_size)
{
    const float* hidden = (const float*)d_in[0];
    const float* w_in   = (const float*)d_in[1];
    const float* b_in   = (const float*)d_in[2];
    const float* rel_w  = (const float*)d_in[3];
    const float* rel_b  = (const float*)d_in[4];
    const float* out_w  = (const float*)d_in[5];
    const float* out_b  = (const float*)d_in[6];
    const int* bkm = (const int*)d_in[9];
    const int* bkn = (const int*)d_in[10];
    float* out = (float*)d_out;

    float *qp, *kp, *vp, *rv, *ctx;
    __half *A2, *Wqkv2, *Wrel2, *Wout2;
    cudaGetSymbolAddress((void**)&qp,  g_q);
    cudaGetSymbolAddress((void**)&kp,  g_k);
    cudaGetSymbolAddress((void**)&vp,  g_v);
    cudaGetSymbolAddress((void**)&rv,  g_relvals);
    cudaGetSymbolAddress((void**)&ctx, g_ctx);
    cudaGetSymbolAddress((void**)&A2,    g_A2);
    cudaGetSymbolAddress((void**)&Wqkv2, g_Wqkv2);
    cudaGetSymbolAddress((void**)&Wrel2, g_Wrel2);
    cudaGetSymbolAddress((void**)&Wout2, g_Wout2);

    cudaFuncSetAttribute(gemm_mma, cudaFuncAttributeMaxDynamicSharedMemorySize, GEMM_SMEM);
    cudaFuncSetAttribute(attn_tc, cudaFuncAttributeMaxDynamicSharedMemorySize,
                         (int)sizeof(AttnTc));

    // 0) fp16 splits
    convert_act<<<ROWS_ALL, 256>>>(hidden, A2);
    convert_w<<<3072, 256>>>(w_in,  Wqkv2);
    convert_w<<<512,  256>>>(rel_w, Wrel2);
    convert_w<<<1024, 256>>>(out_w, Wout2);

    // 1) QKV projection
    gemm_mma<<<dim3(3072 / 128, ROWS_ALL / 128), 256, GEMM_SMEM>>>(
        A2, Wqkv2, b_in, nullptr, 3072, 32, 1, qp, kp, vp);

    // 2) rel values (hi-only K=1024)
    gemm_mma<<<dim3(512 / 128, ROWS_ALL / 128), 256, GEMM_SMEM>>>(
        A2, Wrel2, rel_b, rv, 512, 16, 0, nullptr, nullptr, nullptr);

    // 3) tensor-core flash attention
    attn_tc<<<dim3(8, 64, 3), 128, sizeof(AttnTc)>>>(qp, kp, vp, rv, bkm, bkn, ctx);

    // 4) output projection
    convert_act<<<ROWS_ALL, 256>>>(ctx, A2);
    gemm_mma<<<dim3(1024 / 128, ROWS_ALL / 128), 256, GEMM_SMEM>>>(
        A2, Wout2, out_b, out, 1024, 32, 0, nullptr, nullptr, nullptr);
}